// round 2
// baseline (speedup 1.0000x reference)
#include <cuda_runtime.h>
#include <math.h>
#include <stdint.h>

#define B_  4
#define LQ_ 5440
#define D_  256
#define H_  8
#define HD_ 32
#define FF_ 1024
#define NL_ 6
#define MROWS (B_*LQ_)   // 21760

// ---------------- scratch (device globals; no allocation) ----------------
__device__ float g_pos [MROWS*D_];
__device__ float g_out [MROWS*D_];
__device__ float g_v   [MROWS*D_];
__device__ float g_off [MROWS*D_];
__device__ float g_attn[MROWS*128];
__device__ float g_def [MROWS*D_];
__device__ float g_tmp [MROWS*D_];
__device__ float g_ffn [MROWS*FF_];
__device__ float g_ref [LQ_*2];

// ---------------- flatten + transpose: [B,D,HW] -> rows [base..base+HW) of [B,LQ,D]
__global__ void flatten_kernel(const float* __restrict__ src,
                               const float* __restrict__ lvl,
                               float* __restrict__ dst,
                               int HW, int base)
{
    __shared__ float tile[32][33];
    int b  = blockIdx.z;
    int tx = threadIdx.x, ty = threadIdx.y;
    int hw0 = blockIdx.x * 32;
    int d0  = blockIdx.y * 32;
    const float* sp = src + ((size_t)b * D_) * HW;
    #pragma unroll
    for (int j = 0; j < 32; j += 8) {
        tile[ty + j][tx] = sp[(size_t)(d0 + ty + j) * HW + hw0 + tx];
    }
    __syncthreads();
    float add = (lvl != nullptr) ? lvl[d0 + tx] : 0.0f;
    #pragma unroll
    for (int j = 0; j < 32; j += 8) {
        int hw = hw0 + ty + j;
        dst[((size_t)b * LQ_ + base + hw) * D_ + d0 + tx] = tile[tx][ty + j] + add;
    }
}

// ---------------- reference points ----------------
__global__ void ref_kernel(float* __restrict__ ref)
{
    int q = blockIdx.x * 256 + threadIdx.x;
    if (q >= LQ_) return;
    int base, W;
    if      (q < 4096) { base = 0;    W = 64; }
    else if (q < 5120) { base = 4096; W = 32; }
    else if (q < 5376) { base = 5120; W = 16; }
    else               { base = 5376; W = 8;  }
    int idx = q - base;
    int ry = idx / W, rx = idx % W;
    ref[q * 2 + 0] = (rx + 0.5f) / (float)W;
    ref[q * 2 + 1] = (ry + 0.5f) / (float)W;
}

// ---------------- packed-fp32 helpers ----------------
__device__ __forceinline__ unsigned long long dup_f32(float v)
{
    unsigned int u = __float_as_uint(v);
    return ((unsigned long long)u << 32) | (unsigned long long)u;
}
__device__ __forceinline__ void fma2(unsigned long long& d,
                                     unsigned long long a,
                                     unsigned long long b)
{
    asm("fma.rn.f32x2 %0, %1, %2, %0;" : "+l"(d) : "l"(a), "l"(b));
}
__device__ __forceinline__ float lo_f(unsigned long long v)
{ return __uint_as_float((unsigned int)(v & 0xffffffffull)); }
__device__ __forceinline__ float hi_f(unsigned long long v)
{ return __uint_as_float((unsigned int)(v >> 32)); }

// ---------------- GEMM: C[M,N] = (A (+A2)) @ W + bias, optional relu ----------------
// BM=128 BN=128 BK=16, 256 threads, 8x8 per thread via packed fma.rn.f32x2 (FFMA2).
// A staged in SMEM duplicated so n-pairs ride natural contiguous f32x2 loads.
// Requires: M%128==0, N%128==0, K%16==0.
template<int DO_RELU, int HAS_ADD>
__global__ void __launch_bounds__(256, 2) gemm_kernel(
    const float* __restrict__ A, const float* __restrict__ A2,
    const float* __restrict__ W, const float* __restrict__ bias,
    float* __restrict__ C, int N, int K)
{
    const int BM = 128, BN = 128, BK = 16;
    __shared__ float As[BK][2 * BM];   // duplicated along m: As[k][2m]=As[k][2m+1]=A[m][k]
    __shared__ float Bs[BK][BN];

    int tid = threadIdx.x;
    int bm = blockIdx.y * BM;
    int bn = blockIdx.x * BN;
    int tx = tid & 15;        // n-group (8 cols each)
    int ty = tid >> 4;        // m-group (8 rows each)

    // A loader: row = tid/2, two float4 at k-offsets acol and acol+8
    int arow = tid >> 1;
    int acol = (tid & 1) * 4;
    // B loader: row = tid/16, 8 consecutive n (two float4)
    int brow = tid >> 4;
    int bcol = (tid & 15) * 8;

    const float* Ap  = A + (size_t)(bm + arow) * K + acol;
    const float* A2p = HAS_ADD ? (A2 + (size_t)(bm + arow) * K + acol) : nullptr;
    const float* Bp  = W + (size_t)brow * N + bn + bcol;

    unsigned long long acc[8][4];
    #pragma unroll
    for (int i = 0; i < 8; i++)
        #pragma unroll
        for (int j = 0; j < 4; j++) acc[i][j] = 0ull;

    // prefetch k0 = 0
    float4 ra0 = *(const float4*)(Ap);
    float4 ra1 = *(const float4*)(Ap + 8);
    float4 rb0 = *(const float4*)(Bp);
    float4 rb1 = *(const float4*)(Bp + 4);
    if (HAS_ADD) {
        float4 x0 = *(const float4*)(A2p);
        float4 x1 = *(const float4*)(A2p + 8);
        ra0.x += x0.x; ra0.y += x0.y; ra0.z += x0.z; ra0.w += x0.w;
        ra1.x += x1.x; ra1.y += x1.y; ra1.z += x1.z; ra1.w += x1.w;
    }

    for (int k0 = 0; k0 < K; k0 += BK) {
        // stage current tile into SMEM
        {
            unsigned long long* asrow;
            asrow = (unsigned long long*)&As[acol + 0][2 * arow]; *asrow = dup_f32(ra0.x);
            asrow = (unsigned long long*)&As[acol + 1][2 * arow]; *asrow = dup_f32(ra0.y);
            asrow = (unsigned long long*)&As[acol + 2][2 * arow]; *asrow = dup_f32(ra0.z);
            asrow = (unsigned long long*)&As[acol + 3][2 * arow]; *asrow = dup_f32(ra0.w);
            asrow = (unsigned long long*)&As[acol + 8][2 * arow]; *asrow = dup_f32(ra1.x);
            asrow = (unsigned long long*)&As[acol + 9][2 * arow]; *asrow = dup_f32(ra1.y);
            asrow = (unsigned long long*)&As[acol +10][2 * arow]; *asrow = dup_f32(ra1.z);
            asrow = (unsigned long long*)&As[acol +11][2 * arow]; *asrow = dup_f32(ra1.w);
            *(float4*)&Bs[brow][bcol + 0] = rb0;
            *(float4*)&Bs[brow][bcol + 4] = rb1;
        }
        __syncthreads();

        // prefetch next tile
        if (k0 + BK < K) {
            ra0 = *(const float4*)(Ap + k0 + BK);
            ra1 = *(const float4*)(Ap + k0 + BK + 8);
            rb0 = *(const float4*)(Bp + (size_t)(k0 + BK) * N);
            rb1 = *(const float4*)(Bp + (size_t)(k0 + BK) * N + 4);
            if (HAS_ADD) {
                float4 x0 = *(const float4*)(A2p + k0 + BK);
                float4 x1 = *(const float4*)(A2p + k0 + BK + 8);
                ra0.x += x0.x; ra0.y += x0.y; ra0.z += x0.z; ra0.w += x0.w;
                ra1.x += x1.x; ra1.y += x1.y; ra1.z += x1.z; ra1.w += x1.w;
            }
        }

        // compute
        #pragma unroll
        for (int k = 0; k < BK; k++) {
            const ulonglong2* ap = (const ulonglong2*)&As[k][16 * ty];
            unsigned long long a[8];
            #pragma unroll
            for (int q = 0; q < 4; q++) {
                ulonglong2 av = ap[q];
                a[2 * q + 0] = av.x;
                a[2 * q + 1] = av.y;
            }
            const ulonglong2* bp = (const ulonglong2*)&Bs[k][8 * tx];
            ulonglong2 bv0 = bp[0];
            ulonglong2 bv1 = bp[1];
            unsigned long long b[4] = {bv0.x, bv0.y, bv1.x, bv1.y};
            #pragma unroll
            for (int i = 0; i < 8; i++)
                #pragma unroll
                for (int j = 0; j < 4; j++)
                    fma2(acc[i][j], a[i], b[j]);
        }
        __syncthreads();
    }

    // epilogue
    int n0 = bn + tx * 8;
    float bsv[8];
    #pragma unroll
    for (int j = 0; j < 8; j++) bsv[j] = bias[n0 + j];

    #pragma unroll
    for (int i = 0; i < 8; i++) {
        int m = bm + ty * 8 + i;
        float o[8];
        #pragma unroll
        for (int j = 0; j < 4; j++) {
            o[2 * j + 0] = lo_f(acc[i][j]) + bsv[2 * j + 0];
            o[2 * j + 1] = hi_f(acc[i][j]) + bsv[2 * j + 1];
        }
        if (DO_RELU) {
            #pragma unroll
            for (int j = 0; j < 8; j++) o[j] = fmaxf(o[j], 0.0f);
        }
        float4 w0 = {o[0], o[1], o[2], o[3]};
        float4 w1 = {o[4], o[5], o[6], o[7]};
        *(float4*)(C + (size_t)m * N + n0)     = w0;
        *(float4*)(C + (size_t)m * N + n0 + 4) = w1;
    }
}

// ---------------- LayerNorm with fused residual: out = LN(x + r) ----------------
__global__ void __launch_bounds__(256) ln_kernel(
    const float* __restrict__ x, const float* __restrict__ r,
    const float* __restrict__ g, const float* __restrict__ bta,
    float* __restrict__ out)
{
    int row = blockIdx.x;
    int d = threadIdx.x;
    size_t idx = (size_t)row * D_ + d;
    float v = x[idx] + r[idx];

    __shared__ float sh[8];
    float s = v;
    #pragma unroll
    for (int o = 16; o; o >>= 1) s += __shfl_xor_sync(0xffffffffu, s, o);
    if ((d & 31) == 0) sh[d >> 5] = s;
    __syncthreads();
    float mean = (sh[0]+sh[1]+sh[2]+sh[3]+sh[4]+sh[5]+sh[6]+sh[7]) * (1.0f / D_);
    __syncthreads();

    float c = v - mean;
    float s2 = c * c;
    #pragma unroll
    for (int o = 16; o; o >>= 1) s2 += __shfl_xor_sync(0xffffffffu, s2, o);
    if ((d & 31) == 0) sh[d >> 5] = s2;
    __syncthreads();
    float var = (sh[0]+sh[1]+sh[2]+sh[3]+sh[4]+sh[5]+sh[6]+sh[7]) * (1.0f / D_);

    out[idx] = c * rsqrtf(var + 1e-5f) * g[d] + bta[d];
}

// ---------------- deformable attention (one warp per (b,q,h), lane = channel) ----------
__global__ void __launch_bounds__(256) deform_kernel(
    const float* __restrict__ v,      // [B,LQ,H,HD]
    const float* __restrict__ off,    // [B,LQ,H,L,P,2]
    const float* __restrict__ logits, // [B,LQ,H,16]
    const float* __restrict__ ref,    // [LQ,2]
    float* __restrict__ out)          // [B,LQ,D]
{
    const int dims [4] = {64, 32, 16, 8};
    const int bases[4] = {0, 4096, 5120, 5376};

    int bq   = blockIdx.x;
    int h    = threadIdx.x >> 5;
    int lane = threadIdx.x & 31;
    int b = bq / LQ_;
    int q = bq % LQ_;

    const float* lg = logits + (size_t)bq * 128 + h * 16;
    float xv = (lane < 16) ? lg[lane] : -1e30f;
    float m = xv;
    #pragma unroll
    for (int o = 8; o; o >>= 1) m = fmaxf(m, __shfl_xor_sync(0xffffffffu, m, o));
    float e = (lane < 16) ? __expf(xv - m) : 0.0f;
    float s = e;
    #pragma unroll
    for (int o = 8; o; o >>= 1) s += __shfl_xor_sync(0xffffffffu, s, o);
    float aw = e / s;

    float offv = off[(size_t)bq * 256 + h * 32 + lane];
    float refx = ref[q * 2 + 0];
    float refy = ref[q * 2 + 1];

    const float* vb = v + (size_t)b * LQ_ * 256 + h * HD_ + lane;

    float acc = 0.0f;
    #pragma unroll
    for (int l = 0; l < 4; l++) {
        const int Wl = dims[l];
        const int base = bases[l];
        const float Wf = (float)Wl;
        #pragma unroll
        for (int p = 0; p < 4; p++) {
            int pt = l * 4 + p;
            float ax = __shfl_sync(0xffffffffu, offv, pt * 2 + 0);
            float ay = __shfl_sync(0xffffffffu, offv, pt * 2 + 1);
            float a  = __shfl_sync(0xffffffffu, aw, pt);
            float xf = refx * Wf + ax - 0.5f;
            float yf = refy * Wf + ay - 0.5f;
            float x0f = floorf(xf), y0f = floorf(yf);
            float wx = xf - x0f,   wy = yf - y0f;
            int x0 = (int)x0f, y0 = (int)y0f;
            int x1 = x0 + 1,   y1 = y0 + 1;

            float w00 = (1.f - wy) * (1.f - wx);
            float w01 = (1.f - wy) * wx;
            float w10 = wy * (1.f - wx);
            float w11 = wy * wx;

            if (y0 >= 0 && y0 < Wl) {
                if (x0 >= 0 && x0 < Wl)
                    acc = fmaf(a * w00, vb[(size_t)(base + y0 * Wl + x0) * 256], acc);
                if (x1 >= 0 && x1 < Wl)
                    acc = fmaf(a * w01, vb[(size_t)(base + y0 * Wl + x1) * 256], acc);
            }
            if (y1 >= 0 && y1 < Wl) {
                if (x0 >= 0 && x0 < Wl)
                    acc = fmaf(a * w10, vb[(size_t)(base + y1 * Wl + x0) * 256], acc);
                if (x1 >= 0 && x1 < Wl)
                    acc = fmaf(a * w11, vb[(size_t)(base + y1 * Wl + x1) * 256], acc);
            }
        }
    }
    out[(size_t)bq * 256 + h * HD_ + lane] = acc;
}

// ---------------- host orchestration ----------------
static float* sym_ptr(const void* sym)
{
    void* p = nullptr;
    cudaGetSymbolAddress(&p, sym);
    return (float*)p;
}

extern "C" void kernel_launch(void* const* d_in, const int* in_sizes, int n_in,
                              void* d_out, int out_size)
{
    bool interleaved = (in_sizes[1] == in_sizes[0]);
    const float* srcs[4];
    const float* poss[4];
    for (int l = 0; l < 4; l++) {
        srcs[l] = (const float*)d_in[interleaved ? 2 * l     : l];
        poss[l] = (const float*)d_in[interleaved ? 2 * l + 1 : 4 + l];
    }
    const float* level_embed = (const float*)d_in[8];
    const float* W_off  = (const float*)d_in[9];
    const float* b_off  = (const float*)d_in[10];
    const float* W_attn = (const float*)d_in[11];
    const float* b_attn = (const float*)d_in[12];
    const float* W_v    = (const float*)d_in[13];
    const float* b_v    = (const float*)d_in[14];
    const float* W_o    = (const float*)d_in[15];
    const float* b_o    = (const float*)d_in[16];
    const float* ln1_g  = (const float*)d_in[17];
    const float* ln1_b  = (const float*)d_in[18];
    const float* W_fc1  = (const float*)d_in[19];
    const float* b_fc1  = (const float*)d_in[20];
    const float* W_fc2  = (const float*)d_in[21];
    const float* b_fc2  = (const float*)d_in[22];
    const float* ln2_g  = (const float*)d_in[23];
    const float* ln2_b  = (const float*)d_in[24];

    float* pos  = sym_ptr(g_pos);
    float* out  = sym_ptr(g_out);
    float* vv   = sym_ptr(g_v);
    float* offb = sym_ptr(g_off);
    float* attn = sym_ptr(g_attn);
    float* defo = sym_ptr(g_def);
    float* tmp  = sym_ptr(g_tmp);
    float* ffn  = sym_ptr(g_ffn);
    float* ref  = sym_ptr(g_ref);

    const int HWs[4]   = {4096, 1024, 256, 64};
    const int bases[4] = {0, 4096, 5120, 5376};

    dim3 tb(32, 8);
    for (int l = 0; l < 4; l++) {
        dim3 gr(HWs[l] / 32, D_ / 32, B_);
        flatten_kernel<<<gr, tb>>>(srcs[l], nullptr, out, HWs[l], bases[l]);
        flatten_kernel<<<gr, tb>>>(poss[l], level_embed + l * D_, pos, HWs[l], bases[l]);
    }
    ref_kernel<<<(LQ_ + 255) / 256, 256>>>(ref);

    const int MB = MROWS / 128; // 170
    for (int i = 0; i < NL_; i++) {
        const float* Wv  = W_v    + (size_t)i * D_ * D_;
        const float* bv  = b_v    + (size_t)i * D_;
        const float* Wof = W_off  + (size_t)i * D_ * 256;
        const float* bof = b_off  + (size_t)i * 256;
        const float* Wa  = W_attn + (size_t)i * D_ * 128;
        const float* ba  = b_attn + (size_t)i * 128;
        const float* Wo  = W_o    + (size_t)i * D_ * D_;
        const float* bo  = b_o    + (size_t)i * D_;
        const float* Wf1 = W_fc1  + (size_t)i * D_ * FF_;
        const float* bf1 = b_fc1  + (size_t)i * FF_;
        const float* Wf2 = W_fc2  + (size_t)i * FF_ * D_;
        const float* bf2 = b_fc2  + (size_t)i * D_;

        gemm_kernel<0,0><<<dim3(D_/128,  MB), 256>>>(out, nullptr, Wv,  bv,  vv,   D_,  D_);
        gemm_kernel<0,1><<<dim3(256/128, MB), 256>>>(out, pos,     Wof, bof, offb, 256, D_);
        gemm_kernel<0,1><<<dim3(128/128, MB), 256>>>(out, pos,     Wa,  ba,  attn, 128, D_);

        deform_kernel<<<MROWS, 256>>>(vv, offb, attn, ref, defo);

        gemm_kernel<0,0><<<dim3(D_/128, MB), 256>>>(defo, nullptr, Wo, bo, tmp, D_, D_);
        ln_kernel<<<MROWS, 256>>>(out, tmp, ln1_g + i * D_, ln1_b + i * D_, out);

        gemm_kernel<1,0><<<dim3(FF_/128, MB), 256>>>(out, nullptr, Wf1, bf1, ffn, FF_, D_);
        gemm_kernel<0,0><<<dim3(D_/128,  MB), 256>>>(ffn, nullptr, Wf2, bf2, tmp, D_, FF_);

        float* lnout = (i == NL_ - 1) ? (float*)d_out : out;
        ln_kernel<<<MROWS, 256>>>(out, tmp, ln2_g + i * D_, ln2_b + i * D_, lnout);
    }
}

// round 4
// speedup vs baseline: 2.1366x; 2.1366x over previous
#include <cuda_runtime.h>
#include <math.h>
#include <stdint.h>

#define B_  4
#define LQ_ 5440
#define D_  256
#define H_  8
#define HD_ 32
#define FF_ 1024
#define NL_ 6
#define MROWS (B_*LQ_)   // 21760

// ---------------- scratch (device globals; no allocation) ----------------
__device__ float g_pos [MROWS*D_];
__device__ float g_out [MROWS*D_];
__device__ float g_v   [MROWS*D_];
__device__ float g_off [MROWS*D_];
__device__ float g_attn[MROWS*128];
__device__ float g_def [MROWS*D_];
__device__ float g_tmp [MROWS*D_];
__device__ float g_ffn [MROWS*FF_];
__device__ float g_ref [LQ_*2];

// ---------------- flatten + transpose: [B,D,HW] -> rows of [B,LQ,D] ----------------
__global__ void flatten_kernel(const float* __restrict__ src,
                               const float* __restrict__ lvl,
                               float* __restrict__ dst,
                               int HW, int base)
{
    __shared__ float tile[32][33];
    int b  = blockIdx.z;
    int tx = threadIdx.x, ty = threadIdx.y;
    int hw0 = blockIdx.x * 32;
    int d0  = blockIdx.y * 32;
    const float* sp = src + ((size_t)b * D_) * HW;
    #pragma unroll
    for (int j = 0; j < 32; j += 8)
        tile[ty + j][tx] = sp[(size_t)(d0 + ty + j) * HW + hw0 + tx];
    __syncthreads();
    float add = (lvl != nullptr) ? lvl[d0 + tx] : 0.0f;
    #pragma unroll
    for (int j = 0; j < 32; j += 8) {
        int hw = hw0 + ty + j;
        dst[((size_t)b * LQ_ + base + hw) * D_ + d0 + tx] = tile[tx][ty + j] + add;
    }
}

// ---------------- reference points ----------------
__global__ void ref_kernel(float* __restrict__ ref)
{
    int q = blockIdx.x * 256 + threadIdx.x;
    if (q >= LQ_) return;
    int base, W;
    if      (q < 4096) { base = 0;    W = 64; }
    else if (q < 5120) { base = 4096; W = 32; }
    else if (q < 5376) { base = 5120; W = 16; }
    else               { base = 5376; W = 8;  }
    int idx = q - base;
    int ry = idx / W, rx = idx % W;
    ref[q * 2 + 0] = (rx + 0.5f) / (float)W;
    ref[q * 2 + 1] = (ry + 0.5f) / (float)W;
}

// ---------------- tf32 helpers ----------------
__device__ __forceinline__ uint32_t f2tf32(float x)
{
    uint32_t r;
    asm("cvt.rna.tf32.f32 %0, %1;" : "=r"(r) : "f"(x));
    return r;
}
__device__ __forceinline__ void mma_tf32(float* d, const uint32_t* a, const uint32_t* b)
{
    asm volatile("mma.sync.aligned.m16n8k8.row.col.f32.tf32.tf32.f32 "
        "{%0,%1,%2,%3}, {%4,%5,%6,%7}, {%8,%9}, {%0,%1,%2,%3};"
        : "+f"(d[0]), "+f"(d[1]), "+f"(d[2]), "+f"(d[3])
        : "r"(a[0]), "r"(a[1]), "r"(a[2]), "r"(a[3]), "r"(b[0]), "r"(b[1]));
}

// ---------------- tf32 tensor-core GEMM ----------------
// C[M,N] = (A (+A2)) @ W + bias, optional relu.
// A [M,K] fp32 row-major, W [K,N] fp32 row-major. BM=128 BN=128 BK=16.
// 8 warps: warp_m = w>>2 (64 rows), warp_n = w&3 (32 cols); 4x4 m16n8k8 frags.
#define SMP 136   // padded k-major row stride (words): conflict-free frag loads
template<int DO_RELU, int HAS_ADD>
__global__ void __launch_bounds__(256, 2) tgemm_kernel(
    const float* __restrict__ A, const float* __restrict__ A2,
    const float* __restrict__ W, const float* __restrict__ bias,
    float* __restrict__ C, int N, int K)
{
    __shared__ uint32_t As[2][16][SMP];
    __shared__ uint32_t Bs[2][16][SMP];

    int tid  = threadIdx.x;
    int lane = tid & 31;
    int wrp  = tid >> 5;
    int g    = lane >> 2;     // group id 0..7
    int tg   = lane & 3;      // thread-in-group 0..3

    int bm = blockIdx.y * 128;
    int bn = blockIdx.x * 128;
    int wm = (wrp >> 2) * 64;  // warp m offset in tile
    int wn = (wrp & 3) * 32;   // warp n offset in tile

    // A loader mapping: m_loc = tid>>2 (0..63, +64), kq = tid&3 (4 floats each)
    int mloc = tid >> 2;
    int kq   = tid & 3;
    // B loader mapping: k_loc = tid>>5 (0..7, +8), n_loc = (tid&31)*4
    int kloc = tid >> 5;
    int nloc = (tid & 31) * 4;

    const float* Ap0 = A + (size_t)(bm + mloc) * K + kq * 4;
    const float* Ap1 = Ap0 + (size_t)64 * K;
    const float* A2p0 = HAS_ADD ? (A2 + (size_t)(bm + mloc) * K + kq * 4) : nullptr;
    const float* A2p1 = HAS_ADD ? (A2p0 + (size_t)64 * K) : nullptr;
    const float* Bp0 = W + (size_t)kloc * N + bn + nloc;
    const float* Bp1 = Bp0 + (size_t)8 * N;

    float acc[4][4][4];
    #pragma unroll
    for (int i = 0; i < 4; i++)
        #pragma unroll
        for (int j = 0; j < 4; j++)
            #pragma unroll
            for (int r = 0; r < 4; r++) acc[i][j][r] = 0.0f;

    int NIT = K >> 4;

    float4 va0, va1, vb0, vb1;

    // prefetch tile 0
    va0 = *(const float4*)(Ap0);
    va1 = *(const float4*)(Ap1);
    if (HAS_ADD) {
        float4 x0 = *(const float4*)(A2p0);
        float4 x1 = *(const float4*)(A2p1);
        va0.x += x0.x; va0.y += x0.y; va0.z += x0.z; va0.w += x0.w;
        va1.x += x1.x; va1.y += x1.y; va1.z += x1.z; va1.w += x1.w;
    }
    vb0 = *(const float4*)(Bp0);
    vb1 = *(const float4*)(Bp1);

    // stage tile 0
    {
        As[0][kq * 4 + 0][mloc] = f2tf32(va0.x);
        As[0][kq * 4 + 1][mloc] = f2tf32(va0.y);
        As[0][kq * 4 + 2][mloc] = f2tf32(va0.z);
        As[0][kq * 4 + 3][mloc] = f2tf32(va0.w);
        As[0][kq * 4 + 0][mloc + 64] = f2tf32(va1.x);
        As[0][kq * 4 + 1][mloc + 64] = f2tf32(va1.y);
        As[0][kq * 4 + 2][mloc + 64] = f2tf32(va1.z);
        As[0][kq * 4 + 3][mloc + 64] = f2tf32(va1.w);
        uint4 u0 = {f2tf32(vb0.x), f2tf32(vb0.y), f2tf32(vb0.z), f2tf32(vb0.w)};
        uint4 u1 = {f2tf32(vb1.x), f2tf32(vb1.y), f2tf32(vb1.z), f2tf32(vb1.w)};
        *(uint4*)&Bs[0][kloc][nloc]     = u0;
        *(uint4*)&Bs[0][kloc + 8][nloc] = u1;
    }
    __syncthreads();

    for (int it = 0; it < NIT; it++) {
        int cur = it & 1;
        // prefetch next tile into regs
        if (it + 1 < NIT) {
            int k0 = (it + 1) << 4;
            va0 = *(const float4*)(Ap0 + k0);
            va1 = *(const float4*)(Ap1 + k0);
            if (HAS_ADD) {
                float4 x0 = *(const float4*)(A2p0 + k0);
                float4 x1 = *(const float4*)(A2p1 + k0);
                va0.x += x0.x; va0.y += x0.y; va0.z += x0.z; va0.w += x0.w;
                va1.x += x1.x; va1.y += x1.y; va1.z += x1.z; va1.w += x1.w;
            }
            vb0 = *(const float4*)(Bp0 + (size_t)k0 * N);
            vb1 = *(const float4*)(Bp1 + (size_t)k0 * N);
        }

        // compute on current buffer: two k8 steps
        #pragma unroll
        for (int ks = 0; ks < 16; ks += 8) {
            uint32_t a[4][4];
            #pragma unroll
            for (int mt = 0; mt < 4; mt++) {
                int mb = wm + mt * 16 + g;
                a[mt][0] = As[cur][ks + tg][mb];
                a[mt][1] = As[cur][ks + tg][mb + 8];
                a[mt][2] = As[cur][ks + tg + 4][mb];
                a[mt][3] = As[cur][ks + tg + 4][mb + 8];
            }
            uint32_t b[4][2];
            #pragma unroll
            for (int nt = 0; nt < 4; nt++) {
                int nb = wn + nt * 8 + g;
                b[nt][0] = Bs[cur][ks + tg][nb];
                b[nt][1] = Bs[cur][ks + tg + 4][nb];
            }
            #pragma unroll
            for (int mt = 0; mt < 4; mt++)
                #pragma unroll
                for (int nt = 0; nt < 4; nt++)
                    mma_tf32(acc[mt][nt], a[mt], b[nt]);
        }

        if (it + 1 < NIT) {
            int nxt = (it + 1) & 1;
            __syncthreads();
            As[nxt][kq * 4 + 0][mloc] = f2tf32(va0.x);
            As[nxt][kq * 4 + 1][mloc] = f2tf32(va0.y);
            As[nxt][kq * 4 + 2][mloc] = f2tf32(va0.z);
            As[nxt][kq * 4 + 3][mloc] = f2tf32(va0.w);
            As[nxt][kq * 4 + 0][mloc + 64] = f2tf32(va1.x);
            As[nxt][kq * 4 + 1][mloc + 64] = f2tf32(va1.y);
            As[nxt][kq * 4 + 2][mloc + 64] = f2tf32(va1.z);
            As[nxt][kq * 4 + 3][mloc + 64] = f2tf32(va1.w);
            uint4 u0 = {f2tf32(vb0.x), f2tf32(vb0.y), f2tf32(vb0.z), f2tf32(vb0.w)};
            uint4 u1 = {f2tf32(vb1.x), f2tf32(vb1.y), f2tf32(vb1.z), f2tf32(vb1.w)};
            *(uint4*)&Bs[nxt][kloc][nloc]     = u0;
            *(uint4*)&Bs[nxt][kloc + 8][nloc] = u1;
            __syncthreads();
        }
    }

    // epilogue: bias (+relu), write fp32
    #pragma unroll
    for (int nt = 0; nt < 4; nt++) {
        int n = bn + wn + nt * 8 + 2 * tg;
        float b0 = bias[n], b1 = bias[n + 1];
        #pragma unroll
        for (int mt = 0; mt < 4; mt++) {
            int m0 = bm + wm + mt * 16 + g;
            float2 lo = {acc[mt][nt][0] + b0, acc[mt][nt][1] + b1};
            float2 hi = {acc[mt][nt][2] + b0, acc[mt][nt][3] + b1};
            if (DO_RELU) {
                lo.x = fmaxf(lo.x, 0.f); lo.y = fmaxf(lo.y, 0.f);
                hi.x = fmaxf(hi.x, 0.f); hi.y = fmaxf(hi.y, 0.f);
            }
            *(float2*)(C + (size_t)m0 * N + n)       = lo;
            *(float2*)(C + (size_t)(m0 + 8) * N + n) = hi;
        }
    }
}

// ---------------- LayerNorm with fused residual: out = LN(x + r) ----------------
__global__ void __launch_bounds__(256) ln_kernel(
    const float* __restrict__ x, const float* __restrict__ r,
    const float* __restrict__ g, const float* __restrict__ bta,
    float* __restrict__ out)
{
    int row = blockIdx.x;
    int d = threadIdx.x;
    size_t idx = (size_t)row * D_ + d;
    float v = x[idx] + r[idx];

    __shared__ float sh[8];
    float s = v;
    #pragma unroll
    for (int o = 16; o; o >>= 1) s += __shfl_xor_sync(0xffffffffu, s, o);
    if ((d & 31) == 0) sh[d >> 5] = s;
    __syncthreads();
    float mean = (sh[0]+sh[1]+sh[2]+sh[3]+sh[4]+sh[5]+sh[6]+sh[7]) * (1.0f / D_);
    __syncthreads();

    float c = v - mean;
    float s2 = c * c;
    #pragma unroll
    for (int o = 16; o; o >>= 1) s2 += __shfl_xor_sync(0xffffffffu, s2, o);
    if ((d & 31) == 0) sh[d >> 5] = s2;
    __syncthreads();
    float var = (sh[0]+sh[1]+sh[2]+sh[3]+sh[4]+sh[5]+sh[6]+sh[7]) * (1.0f / D_);

    out[idx] = c * rsqrtf(var + 1e-5f) * g[d] + bta[d];
}

// ---------------- deformable attention (one warp per (b,q,h), lane = channel) ----------
__global__ void __launch_bounds__(256) deform_kernel(
    const float* __restrict__ v,
    const float* __restrict__ off,
    const float* __restrict__ logits,
    const float* __restrict__ ref,
    float* __restrict__ out)
{
    const int dims [4] = {64, 32, 16, 8};
    const int bases[4] = {0, 4096, 5120, 5376};

    int bq   = blockIdx.x;
    int h    = threadIdx.x >> 5;
    int lane = threadIdx.x & 31;
    int b = bq / LQ_;
    int q = bq % LQ_;

    const float* lg = logits + (size_t)bq * 128 + h * 16;
    float xv = (lane < 16) ? lg[lane] : -1e30f;
    float m = xv;
    #pragma unroll
    for (int o = 8; o; o >>= 1) m = fmaxf(m, __shfl_xor_sync(0xffffffffu, m, o));
    float e = (lane < 16) ? __expf(xv - m) : 0.0f;
    float s = e;
    #pragma unroll
    for (int o = 8; o; o >>= 1) s += __shfl_xor_sync(0xffffffffu, s, o);
    float aw = e / s;

    float offv = off[(size_t)bq * 256 + h * 32 + lane];
    float refx = ref[q * 2 + 0];
    float refy = ref[q * 2 + 1];

    const float* vb = v + (size_t)b * LQ_ * 256 + h * HD_ + lane;

    float acc = 0.0f;
    #pragma unroll
    for (int l = 0; l < 4; l++) {
        const int Wl = dims[l];
        const int base = bases[l];
        const float Wf = (float)Wl;
        #pragma unroll
        for (int p = 0; p < 4; p++) {
            int pt = l * 4 + p;
            float ax = __shfl_sync(0xffffffffu, offv, pt * 2 + 0);
            float ay = __shfl_sync(0xffffffffu, offv, pt * 2 + 1);
            float a  = __shfl_sync(0xffffffffu, aw, pt);
            float xf = refx * Wf + ax - 0.5f;
            float yf = refy * Wf + ay - 0.5f;
            float x0f = floorf(xf), y0f = floorf(yf);
            float wx = xf - x0f,   wy = yf - y0f;
            int x0 = (int)x0f, y0 = (int)y0f;
            int x1 = x0 + 1,   y1 = y0 + 1;

            float w00 = (1.f - wy) * (1.f - wx);
            float w01 = (1.f - wy) * wx;
            float w10 = wy * (1.f - wx);
            float w11 = wy * wx;

            if (y0 >= 0 && y0 < Wl) {
                if (x0 >= 0 && x0 < Wl)
                    acc = fmaf(a * w00, vb[(size_t)(base + y0 * Wl + x0) * 256], acc);
                if (x1 >= 0 && x1 < Wl)
                    acc = fmaf(a * w01, vb[(size_t)(base + y0 * Wl + x1) * 256], acc);
            }
            if (y1 >= 0 && y1 < Wl) {
                if (x0 >= 0 && x0 < Wl)
                    acc = fmaf(a * w10, vb[(size_t)(base + y1 * Wl + x0) * 256], acc);
                if (x1 >= 0 && x1 < Wl)
                    acc = fmaf(a * w11, vb[(size_t)(base + y1 * Wl + x1) * 256], acc);
            }
        }
    }
    out[(size_t)bq * 256 + h * HD_ + lane] = acc;
}

// ---------------- host orchestration ----------------
static float* sym_ptr(const void* sym)
{
    void* p = nullptr;
    cudaGetSymbolAddress(&p, sym);
    return (float*)p;
}

extern "C" void kernel_launch(void* const* d_in, const int* in_sizes, int n_in,
                              void* d_out, int out_size)
{
    bool interleaved = (in_sizes[1] == in_sizes[0]);
    const float* srcs[4];
    const float* poss[4];
    for (int l = 0; l < 4; l++) {
        srcs[l] = (const float*)d_in[interleaved ? 2 * l     : l];
        poss[l] = (const float*)d_in[interleaved ? 2 * l + 1 : 4 + l];
    }
    const float* level_embed = (const float*)d_in[8];
    const float* W_off  = (const float*)d_in[9];
    const float* b_off  = (const float*)d_in[10];
    const float* W_attn = (const float*)d_in[11];
    const float* b_attn = (const float*)d_in[12];
    const float* W_v    = (const float*)d_in[13];
    const float* b_v    = (const float*)d_in[14];
    const float* W_o    = (const float*)d_in[15];
    const float* b_o    = (const float*)d_in[16];
    const float* ln1_g  = (const float*)d_in[17];
    const float* ln1_b  = (const float*)d_in[18];
    const float* W_fc1  = (const float*)d_in[19];
    const float* b_fc1  = (const float*)d_in[20];
    const float* W_fc2  = (const float*)d_in[21];
    const float* b_fc2  = (const float*)d_in[22];
    const float* ln2_g  = (const float*)d_in[23];
    const float* ln2_b  = (const float*)d_in[24];

    float* pos  = sym_ptr(g_pos);
    float* out  = sym_ptr(g_out);
    float* vv   = sym_ptr(g_v);
    float* offb = sym_ptr(g_off);
    float* attn = sym_ptr(g_attn);
    float* defo = sym_ptr(g_def);
    float* tmp  = sym_ptr(g_tmp);
    float* ffn  = sym_ptr(g_ffn);
    float* ref  = sym_ptr(g_ref);

    const int HWs[4]   = {4096, 1024, 256, 64};
    const int bases[4] = {0, 4096, 5120, 5376};

    dim3 tb(32, 8);
    for (int l = 0; l < 4; l++) {
        dim3 gr(HWs[l] / 32, D_ / 32, B_);
        flatten_kernel<<<gr, tb>>>(srcs[l], nullptr, out, HWs[l], bases[l]);
        flatten_kernel<<<gr, tb>>>(poss[l], level_embed + l * D_, pos, HWs[l], bases[l]);
    }
    ref_kernel<<<(LQ_ + 255) / 256, 256>>>(ref);

    const int MB = MROWS / 128; // 170
    for (int i = 0; i < NL_; i++) {
        const float* Wv  = W_v    + (size_t)i * D_ * D_;
        const float* bv  = b_v    + (size_t)i * D_;
        const float* Wof = W_off  + (size_t)i * D_ * 256;
        const float* bof = b_off  + (size_t)i * 256;
        const float* Wa  = W_attn + (size_t)i * D_ * 128;
        const float* ba  = b_attn + (size_t)i * 128;
        const float* Wo  = W_o    + (size_t)i * D_ * D_;
        const float* bo  = b_o    + (size_t)i * D_;
        const float* Wf1 = W_fc1  + (size_t)i * D_ * FF_;
        const float* bf1 = b_fc1  + (size_t)i * FF_;
        const float* Wf2 = W_fc2  + (size_t)i * FF_ * D_;
        const float* bf2 = b_fc2  + (size_t)i * D_;

        tgemm_kernel<0,0><<<dim3(2, MB), 256>>>(out, nullptr, Wv,  bv,  vv,   256, 256);
        tgemm_kernel<0,1><<<dim3(2, MB), 256>>>(out, pos,     Wof, bof, offb, 256, 256);
        tgemm_kernel<0,1><<<dim3(1, MB), 256>>>(out, pos,     Wa,  ba,  attn, 128, 256);

        deform_kernel<<<MROWS, 256>>>(vv, offb, attn, ref, defo);

        tgemm_kernel<0,0><<<dim3(2, MB), 256>>>(defo, nullptr, Wo, bo, tmp, 256, 256);
        ln_kernel<<<MROWS, 256>>>(out, tmp, ln1_g + i * D_, ln1_b + i * D_, out);

        tgemm_kernel<1,0><<<dim3(8, MB), 256>>>(out, nullptr, Wf1, bf1, ffn, 1024, 256);
        tgemm_kernel<0,0><<<dim3(2, MB), 256>>>(ffn, nullptr, Wf2, bf2, tmp, 256, 1024);

        float* lnout = (i == NL_ - 1) ? (float*)d_out : out;
        ln_kernel<<<MROWS, 256>>>(out, tmp, ln2_g + i * D_, ln2_b + i * D_, lnout);
    }
}

// round 5
// speedup vs baseline: 2.4165x; 1.1310x over previous
#include <cuda_runtime.h>
#include <math.h>
#include <stdint.h>

#define B_  4
#define LQ_ 5440
#define D_  256
#define H_  8
#define HD_ 32
#define FF_ 1024
#define NL_ 6
#define MROWS (B_*LQ_)   // 21760

// ---------------- scratch (device globals; no allocation) ----------------
__device__ float g_pos [MROWS*D_];
__device__ float g_out [MROWS*D_];
__device__ float g_v   [MROWS*D_];
__device__ float g_oa  [MROWS*384];   // combined [off(256) | attn logits(128)]
__device__ float g_def [MROWS*D_];
__device__ float g_tmp [MROWS*D_];
__device__ float g_ffn [MROWS*FF_];
__device__ float g_ref [LQ_*2];
__device__ float g_wc  [NL_*256*384]; // prepacked [W_off | W_attn]
__device__ float g_bc  [NL_*384];

// ---------------- flatten + transpose: [B,D,HW] -> rows of [B,LQ,D] ----------------
__global__ void flatten_kernel(const float* __restrict__ src,
                               const float* __restrict__ lvl,
                               float* __restrict__ dst,
                               int HW, int base)
{
    __shared__ float tile[32][33];
    int b  = blockIdx.z;
    int tx = threadIdx.x, ty = threadIdx.y;
    int hw0 = blockIdx.x * 32;
    int d0  = blockIdx.y * 32;
    const float* sp = src + ((size_t)b * D_) * HW;
    #pragma unroll
    for (int j = 0; j < 32; j += 8)
        tile[ty + j][tx] = sp[(size_t)(d0 + ty + j) * HW + hw0 + tx];
    __syncthreads();
    float add = (lvl != nullptr) ? lvl[d0 + tx] : 0.0f;
    #pragma unroll
    for (int j = 0; j < 32; j += 8) {
        int hw = hw0 + ty + j;
        dst[((size_t)b * LQ_ + base + hw) * D_ + d0 + tx] = tile[tx][ty + j] + add;
    }
}

// ---------------- reference points ----------------
__global__ void ref_kernel(float* __restrict__ ref)
{
    int q = blockIdx.x * 256 + threadIdx.x;
    if (q >= LQ_) return;
    int base, W;
    if      (q < 4096) { base = 0;    W = 64; }
    else if (q < 5120) { base = 4096; W = 32; }
    else if (q < 5376) { base = 5120; W = 16; }
    else               { base = 5376; W = 8;  }
    int idx = q - base;
    int ry = idx / W, rx = idx % W;
    ref[q * 2 + 0] = (rx + 0.5f) / (float)W;
    ref[q * 2 + 1] = (ry + 0.5f) / (float)W;
}

// ---------------- weight prepack: [Woff | Wattn] -> [NL,256,384] ----------------
__global__ void wcomb_kernel(const float* __restrict__ Woff,
                             const float* __restrict__ Wattn,
                             const float* __restrict__ boff,
                             const float* __restrict__ battn,
                             float* __restrict__ Wc, float* __restrict__ bc)
{
    int idx = blockIdx.x * 256 + threadIdx.x;
    int total = NL_ * 256 * 384;
    if (idx < total) {
        int n = idx % 384;
        int k = (idx / 384) % 256;
        int l = idx / (384 * 256);
        float v = (n < 256) ? Woff[((size_t)l * 256 + k) * 256 + n]
                            : Wattn[((size_t)l * 256 + k) * 128 + (n - 256)];
        Wc[idx] = v;
    }
    if (idx < NL_ * 384) {
        int n = idx % 384;
        int l = idx / 384;
        bc[idx] = (n < 256) ? boff[l * 256 + n] : battn[l * 128 + (n - 256)];
    }
}

// ---------------- mma helper ----------------
__device__ __forceinline__ void mma_tf32(float* d, const uint32_t* a, const uint32_t* b)
{
    asm volatile("mma.sync.aligned.m16n8k8.row.col.f32.tf32.tf32.f32 "
        "{%0,%1,%2,%3}, {%4,%5,%6,%7}, {%8,%9}, {%0,%1,%2,%3};"
        : "+f"(d[0]), "+f"(d[1]), "+f"(d[2]), "+f"(d[3])
        : "r"(a[0]), "r"(a[1]), "r"(a[2]), "r"(a[3]), "r"(b[0]), "r"(b[1]));
}

// ---------------- tf32 tensor-core GEMM ----------------
// C[M,N] = (A (+A2)) @ W + bias, optional relu. BM=128 BN=128 BK=16, 8 warps.
// A SMEM: fragment-packed quads [(k,m),(k,m+8),(k+4,m),(k+4,m+8)] -> one LDS.128/frag.
//   chunk(kg,tk,mgrp,p) = kg*264 + tk*66 + mgrp*8 + p   (chunk = 4 words = 16B)
// B SMEM: plain [k][n] stride 136 words.
#define SMB 136
template<int DO_RELU, int HAS_ADD>
__global__ void __launch_bounds__(256, 2) tgemm_kernel(
    const float* __restrict__ A, const float* __restrict__ A2,
    const float* __restrict__ W, const float* __restrict__ bias,
    float* __restrict__ C, int N, int K)
{
    __shared__ uint32_t As[2][2112];        // 2*264 chunks * 4 words
    __shared__ uint32_t Bs[2][16][SMB];

    int tid  = threadIdx.x;
    int lane = tid & 31;
    int wrp  = tid >> 5;
    int g    = lane >> 2;
    int tg   = lane & 3;

    int bm = blockIdx.y * 128;
    int bn = blockIdx.x * 128;
    int wm = (wrp >> 2) * 64;
    int wn = (wrp & 3) * 32;

    // A loader: m = tid>>2 (0..63 and +64), kq = tid&3 -> k = kq*4+j
    int mloc = tid >> 2;
    int kq   = tid & 3;
    // B loader: kloc = tid>>5 (0..7, +8), nloc = (tid&31)*4
    int kloc = tid >> 5;
    int nloc = (tid & 31) * 4;

    const float* Ap0  = A + (size_t)(bm + mloc) * K + kq * 4;
    const float* Ap1  = Ap0 + (size_t)64 * K;
    const float* A2p0 = HAS_ADD ? (A2 + (size_t)(bm + mloc) * K + kq * 4) : nullptr;
    const float* A2p1 = HAS_ADD ? (A2p0 + (size_t)64 * K) : nullptr;
    const float* Bp0  = W + (size_t)kloc * N + bn + nloc;
    const float* Bp1  = Bp0 + (size_t)8 * N;

    // precomputed A staging addresses (word offsets into As[buf])
    int kg = kq >> 1, uk = kq & 1;
    int st0, st1;
    {
        int mgrp = mloc >> 4, p = mloc & 7, mh = (mloc >> 3) & 1;
        st0 = (kg * 264 + mgrp * 8 + p) * 4 + uk * 2 + mh;
        int m2 = mloc + 64;
        int mgrp2 = m2 >> 4, p2 = m2 & 7, mh2 = (m2 >> 3) & 1;
        st1 = (kg * 264 + mgrp2 * 8 + p2) * 4 + uk * 2 + mh2;
    }

    float acc[4][4][4];
    #pragma unroll
    for (int i = 0; i < 4; i++)
        #pragma unroll
        for (int j = 0; j < 4; j++)
            #pragma unroll
            for (int r = 0; r < 4; r++) acc[i][j][r] = 0.0f;

    int NIT = K >> 4;

    float4 va0, va1, vb0, vb1;

    va0 = *(const float4*)(Ap0);
    va1 = *(const float4*)(Ap1);
    if (HAS_ADD) {
        float4 x0 = *(const float4*)(A2p0);
        float4 x1 = *(const float4*)(A2p1);
        va0.x += x0.x; va0.y += x0.y; va0.z += x0.z; va0.w += x0.w;
        va1.x += x1.x; va1.y += x1.y; va1.z += x1.z; va1.w += x1.w;
    }
    vb0 = *(const float4*)(Bp0);
    vb1 = *(const float4*)(Bp1);

    // stage tile 0
    {
        uint32_t* s = &As[0][0];
        s[st0 +   0] = __float_as_uint(va0.x);
        s[st0 + 264] = __float_as_uint(va0.y);
        s[st0 + 528] = __float_as_uint(va0.z);
        s[st0 + 792] = __float_as_uint(va0.w);
        s[st1 +   0] = __float_as_uint(va1.x);
        s[st1 + 264] = __float_as_uint(va1.y);
        s[st1 + 528] = __float_as_uint(va1.z);
        s[st1 + 792] = __float_as_uint(va1.w);
        *(float4*)&Bs[0][kloc][nloc]     = vb0;
        *(float4*)&Bs[0][kloc + 8][nloc] = vb1;
    }
    __syncthreads();

    for (int it = 0; it < NIT; it++) {
        int cur = it & 1;
        if (it + 1 < NIT) {
            int k0 = (it + 1) << 4;
            va0 = *(const float4*)(Ap0 + k0);
            va1 = *(const float4*)(Ap1 + k0);
            if (HAS_ADD) {
                float4 x0 = *(const float4*)(A2p0 + k0);
                float4 x1 = *(const float4*)(A2p1 + k0);
                va0.x += x0.x; va0.y += x0.y; va0.z += x0.z; va0.w += x0.w;
                va1.x += x1.x; va1.y += x1.y; va1.z += x1.z; va1.w += x1.w;
            }
            vb0 = *(const float4*)(Bp0 + (size_t)k0 * N);
            vb1 = *(const float4*)(Bp1 + (size_t)k0 * N);
        }

        #pragma unroll
        for (int ksg = 0; ksg < 2; ksg++) {     // k-step group: kg = ksg, k base = ksg*8
            // A fragments: one LDS.128 per mt
            const uint4* abase = (const uint4*)&As[cur][(ksg * 264 + tg * 66) * 4];
            int mgb = (wm >> 4) * 8 + g;
            uint32_t a[4][4];
            #pragma unroll
            for (int mt = 0; mt < 4; mt++) {
                uint4 v = abase[mgb + mt * 8];
                a[mt][0] = v.x; a[mt][1] = v.y; a[mt][2] = v.z; a[mt][3] = v.w;
            }
            int ks = ksg * 8;
            uint32_t b[4][2];
            #pragma unroll
            for (int nt = 0; nt < 4; nt++) {
                int nb = wn + nt * 8 + g;
                b[nt][0] = Bs[cur][ks + tg][nb];
                b[nt][1] = Bs[cur][ks + tg + 4][nb];
            }
            #pragma unroll
            for (int mt = 0; mt < 4; mt++)
                #pragma unroll
                for (int nt = 0; nt < 4; nt++)
                    mma_tf32(acc[mt][nt], a[mt], b[nt]);
        }

        if (it + 1 < NIT) {
            int nxt = (it + 1) & 1;
            __syncthreads();
            uint32_t* s = &As[nxt][0];
            s[st0 +   0] = __float_as_uint(va0.x);
            s[st0 + 264] = __float_as_uint(va0.y);
            s[st0 + 528] = __float_as_uint(va0.z);
            s[st0 + 792] = __float_as_uint(va0.w);
            s[st1 +   0] = __float_as_uint(va1.x);
            s[st1 + 264] = __float_as_uint(va1.y);
            s[st1 + 528] = __float_as_uint(va1.z);
            s[st1 + 792] = __float_as_uint(va1.w);
            *(float4*)&Bs[nxt][kloc][nloc]     = vb0;
            *(float4*)&Bs[nxt][kloc + 8][nloc] = vb1;
            __syncthreads();
        }
    }

    // epilogue: bias (+relu), fp32 out
    #pragma unroll
    for (int nt = 0; nt < 4; nt++) {
        int n = bn + wn + nt * 8 + 2 * tg;
        float b0 = bias[n], b1 = bias[n + 1];
        #pragma unroll
        for (int mt = 0; mt < 4; mt++) {
            int m0 = bm + wm + mt * 16 + g;
            float2 lo = {acc[mt][nt][0] + b0, acc[mt][nt][1] + b1};
            float2 hi = {acc[mt][nt][2] + b0, acc[mt][nt][3] + b1};
            if (DO_RELU) {
                lo.x = fmaxf(lo.x, 0.f); lo.y = fmaxf(lo.y, 0.f);
                hi.x = fmaxf(hi.x, 0.f); hi.y = fmaxf(hi.y, 0.f);
            }
            *(float2*)(C + (size_t)m0 * N + n)       = lo;
            *(float2*)(C + (size_t)(m0 + 8) * N + n) = hi;
        }
    }
}

// ---------------- LayerNorm with fused residual: out = LN(x + r) ----------------
__global__ void __launch_bounds__(256) ln_kernel(
    const float* __restrict__ x, const float* __restrict__ r,
    const float* __restrict__ g, const float* __restrict__ bta,
    float* __restrict__ out)
{
    int row = blockIdx.x;
    int d = threadIdx.x;
    size_t idx = (size_t)row * D_ + d;
    float v = x[idx] + r[idx];

    __shared__ float sh[8];
    float s = v;
    #pragma unroll
    for (int o = 16; o; o >>= 1) s += __shfl_xor_sync(0xffffffffu, s, o);
    if ((d & 31) == 0) sh[d >> 5] = s;
    __syncthreads();
    float mean = (sh[0]+sh[1]+sh[2]+sh[3]+sh[4]+sh[5]+sh[6]+sh[7]) * (1.0f / D_);
    __syncthreads();

    float c = v - mean;
    float s2 = c * c;
    #pragma unroll
    for (int o = 16; o; o >>= 1) s2 += __shfl_xor_sync(0xffffffffu, s2, o);
    if ((d & 31) == 0) sh[d >> 5] = s2;
    __syncthreads();
    float var = (sh[0]+sh[1]+sh[2]+sh[3]+sh[4]+sh[5]+sh[6]+sh[7]) * (1.0f / D_);

    out[idx] = c * rsqrtf(var + 1e-5f) * g[d] + bta[d];
}

// ---------------- deformable attention (one warp per (b,q,h)) ----------------
// oa: combined per-row [off(256) | logits(128)], stride 384
__global__ void __launch_bounds__(256) deform_kernel(
    const float* __restrict__ v,
    const float* __restrict__ oa,
    const float* __restrict__ ref,
    float* __restrict__ out)
{
    const int dims [4] = {64, 32, 16, 8};
    const int bases[4] = {0, 4096, 5120, 5376};

    int bq   = blockIdx.x;
    int h    = threadIdx.x >> 5;
    int lane = threadIdx.x & 31;
    int b = bq / LQ_;
    int q = bq % LQ_;

    const float* lg = oa + (size_t)bq * 384 + 256 + h * 16;
    float xv = (lane < 16) ? lg[lane] : -1e30f;
    float m = xv;
    #pragma unroll
    for (int o = 8; o; o >>= 1) m = fmaxf(m, __shfl_xor_sync(0xffffffffu, m, o));
    float e = (lane < 16) ? __expf(xv - m) : 0.0f;
    float s = e;
    #pragma unroll
    for (int o = 8; o; o >>= 1) s += __shfl_xor_sync(0xffffffffu, s, o);
    float aw = e / s;

    float offv = oa[(size_t)bq * 384 + h * 32 + lane];
    float refx = ref[q * 2 + 0];
    float refy = ref[q * 2 + 1];

    const float* vb = v + (size_t)b * LQ_ * 256 + h * HD_ + lane;

    float acc = 0.0f;
    #pragma unroll
    for (int l = 0; l < 4; l++) {
        const int Wl = dims[l];
        const int base = bases[l];
        const float Wf = (float)Wl;
        #pragma unroll
        for (int p = 0; p < 4; p++) {
            int pt = l * 4 + p;
            float ax = __shfl_sync(0xffffffffu, offv, pt * 2 + 0);
            float ay = __shfl_sync(0xffffffffu, offv, pt * 2 + 1);
            float a  = __shfl_sync(0xffffffffu, aw, pt);
            float xf = refx * Wf + ax - 0.5f;
            float yf = refy * Wf + ay - 0.5f;
            float x0f = floorf(xf), y0f = floorf(yf);
            float wx = xf - x0f,   wy = yf - y0f;
            int x0 = (int)x0f, y0 = (int)y0f;
            int x1 = x0 + 1,   y1 = y0 + 1;

            float w00 = (1.f - wy) * (1.f - wx);
            float w01 = (1.f - wy) * wx;
            float w10 = wy * (1.f - wx);
            float w11 = wy * wx;

            if (y0 >= 0 && y0 < Wl) {
                if (x0 >= 0 && x0 < Wl)
                    acc = fmaf(a * w00, vb[(size_t)(base + y0 * Wl + x0) * 256], acc);
                if (x1 >= 0 && x1 < Wl)
                    acc = fmaf(a * w01, vb[(size_t)(base + y0 * Wl + x1) * 256], acc);
            }
            if (y1 >= 0 && y1 < Wl) {
                if (x0 >= 0 && x0 < Wl)
                    acc = fmaf(a * w10, vb[(size_t)(base + y1 * Wl + x0) * 256], acc);
                if (x1 >= 0 && x1 < Wl)
                    acc = fmaf(a * w11, vb[(size_t)(base + y1 * Wl + x1) * 256], acc);
            }
        }
    }
    out[(size_t)bq * 256 + h * HD_ + lane] = acc;
}

// ---------------- host orchestration ----------------
static float* sym_ptr(const void* sym)
{
    void* p = nullptr;
    cudaGetSymbolAddress(&p, sym);
    return (float*)p;
}

extern "C" void kernel_launch(void* const* d_in, const int* in_sizes, int n_in,
                              void* d_out, int out_size)
{
    bool interleaved = (in_sizes[1] == in_sizes[0]);
    const float* srcs[4];
    const float* poss[4];
    for (int l = 0; l < 4; l++) {
        srcs[l] = (const float*)d_in[interleaved ? 2 * l     : l];
        poss[l] = (const float*)d_in[interleaved ? 2 * l + 1 : 4 + l];
    }
    const float* level_embed = (const float*)d_in[8];
    const float* W_off  = (const float*)d_in[9];
    const float* b_off  = (const float*)d_in[10];
    const float* W_attn = (const float*)d_in[11];
    const float* b_attn = (const float*)d_in[12];
    const float* W_v    = (const float*)d_in[13];
    const float* b_v    = (const float*)d_in[14];
    const float* W_o    = (const float*)d_in[15];
    const float* b_o    = (const float*)d_in[16];
    const float* ln1_g  = (const float*)d_in[17];
    const float* ln1_b  = (const float*)d_in[18];
    const float* W_fc1  = (const float*)d_in[19];
    const float* b_fc1  = (const float*)d_in[20];
    const float* W_fc2  = (const float*)d_in[21];
    const float* b_fc2  = (const float*)d_in[22];
    const float* ln2_g  = (const float*)d_in[23];
    const float* ln2_b  = (const float*)d_in[24];

    float* pos  = sym_ptr(g_pos);
    float* out  = sym_ptr(g_out);
    float* vv   = sym_ptr(g_v);
    float* oa   = sym_ptr(g_oa);
    float* defo = sym_ptr(g_def);
    float* tmp  = sym_ptr(g_tmp);
    float* ffn  = sym_ptr(g_ffn);
    float* ref  = sym_ptr(g_ref);
    float* wc   = sym_ptr(g_wc);
    float* bc   = sym_ptr(g_bc);

    const int HWs[4]   = {4096, 1024, 256, 64};
    const int bases[4] = {0, 4096, 5120, 5376};

    dim3 tb(32, 8);
    for (int l = 0; l < 4; l++) {
        dim3 gr(HWs[l] / 32, D_ / 32, B_);
        flatten_kernel<<<gr, tb>>>(srcs[l], nullptr, out, HWs[l], bases[l]);
        flatten_kernel<<<gr, tb>>>(poss[l], level_embed + l * D_, pos, HWs[l], bases[l]);
    }
    ref_kernel<<<(LQ_ + 255) / 256, 256>>>(ref);
    wcomb_kernel<<<(NL_ * 256 * 384 + 255) / 256, 256>>>(W_off, W_attn, b_off, b_attn, wc, bc);

    const int MB = MROWS / 128; // 170
    for (int i = 0; i < NL_; i++) {
        const float* Wv  = W_v   + (size_t)i * D_ * D_;
        const float* bv  = b_v   + (size_t)i * D_;
        const float* Wc  = wc    + (size_t)i * 256 * 384;
        const float* Bc  = bc    + (size_t)i * 384;
        const float* Wo  = W_o   + (size_t)i * D_ * D_;
        const float* bo  = b_o   + (size_t)i * D_;
        const float* Wf1 = W_fc1 + (size_t)i * D_ * FF_;
        const float* bf1 = b_fc1 + (size_t)i * FF_;
        const float* Wf2 = W_fc2 + (size_t)i * FF_ * D_;
        const float* bf2 = b_fc2 + (size_t)i * D_;

        tgemm_kernel<0,0><<<dim3(2, MB), 256>>>(out, nullptr, Wv, bv, vv,  256, 256);
        tgemm_kernel<0,1><<<dim3(3, MB), 256>>>(out, pos,     Wc, Bc, oa,  384, 256);

        deform_kernel<<<MROWS, 256>>>(vv, oa, ref, defo);

        tgemm_kernel<0,0><<<dim3(2, MB), 256>>>(defo, nullptr, Wo, bo, tmp, 256, 256);
        ln_kernel<<<MROWS, 256>>>(out, tmp, ln1_g + i * D_, ln1_b + i * D_, out);

        tgemm_kernel<1,0><<<dim3(8, MB), 256>>>(out, nullptr, Wf1, bf1, ffn, 1024, 256);
        tgemm_kernel<0,0><<<dim3(2, MB), 256>>>(ffn, nullptr, Wf2, bf2, tmp, 256, 1024);

        float* lnout = (i == NL_ - 1) ? (float*)d_out : out;
        ln_kernel<<<MROWS, 256>>>(out, tmp, ln2_g + i * D_, ln2_b + i * D_, lnout);
    }
}

// round 6
// speedup vs baseline: 2.4494x; 1.0136x over previous
#include <cuda_runtime.h>
#include <math.h>
#include <stdint.h>

#define B_  4
#define LQ_ 5440
#define D_  256
#define H_  8
#define HD_ 32
#define FF_ 1024
#define NL_ 6
#define MROWS (B_*LQ_)   // 21760

// ---------------- scratch (device globals; no allocation) ----------------
__device__ float g_pos [MROWS*D_];
__device__ float g_out [MROWS*D_];
__device__ float g_voa [MROWS*640];   // fused [v(256) | off(256) | logits(128)]
__device__ float g_def [MROWS*D_];
__device__ float g_tmp [MROWS*D_];
__device__ float g_ffn [MROWS*FF_];
__device__ float g_ref [LQ_*2];
__device__ float g_wc  [NL_*256*640]; // prepacked [W_v | W_off | W_attn]
__device__ float g_bc  [NL_*640];

// ---------------- fused flatten: all 4 levels, src+pos in one launch ----------------
// grid = (170 hw-tiles, D/32, B); per block: 32x32 transpose of src -> out and pos -> pos.
__global__ void flatten_all_kernel(
    const float* __restrict__ s0, const float* __restrict__ s1,
    const float* __restrict__ s2, const float* __restrict__ s3,
    const float* __restrict__ p0, const float* __restrict__ p1,
    const float* __restrict__ p2, const float* __restrict__ p3,
    const float* __restrict__ lvl_emb,
    float* __restrict__ dsrc, float* __restrict__ dpos)
{
    __shared__ float ts[32][33];
    __shared__ float tp[32][33];

    int t = blockIdx.x;
    int level, hwt, HW, base;
    if      (t < 128) { level = 0; hwt = t;       HW = 4096; base = 0;    }
    else if (t < 160) { level = 1; hwt = t - 128; HW = 1024; base = 4096; }
    else if (t < 168) { level = 2; hwt = t - 160; HW = 256;  base = 5120; }
    else              { level = 3; hwt = t - 168; HW = 64;   base = 5376; }

    const float* src = (level == 0) ? s0 : (level == 1) ? s1 : (level == 2) ? s2 : s3;
    const float* pos = (level == 0) ? p0 : (level == 1) ? p1 : (level == 2) ? p2 : p3;

    int b  = blockIdx.z;
    int tx = threadIdx.x, ty = threadIdx.y;
    int hw0 = hwt * 32;
    int d0  = blockIdx.y * 32;

    const float* sp = src + ((size_t)b * D_) * HW;
    const float* pp = pos + ((size_t)b * D_) * HW;
    #pragma unroll
    for (int j = 0; j < 32; j += 8) {
        ts[ty + j][tx] = sp[(size_t)(d0 + ty + j) * HW + hw0 + tx];
        tp[ty + j][tx] = pp[(size_t)(d0 + ty + j) * HW + hw0 + tx];
    }
    __syncthreads();
    float add = lvl_emb[level * D_ + d0 + tx];
    #pragma unroll
    for (int j = 0; j < 32; j += 8) {
        int hw = hw0 + ty + j;
        size_t row = ((size_t)b * LQ_ + base + hw) * D_ + d0 + tx;
        dsrc[row] = ts[tx][ty + j];
        dpos[row] = tp[tx][ty + j] + add;
    }
}

// ---------------- reference points ----------------
__global__ void ref_kernel(float* __restrict__ ref)
{
    int q = blockIdx.x * 256 + threadIdx.x;
    if (q >= LQ_) return;
    int base, W;
    if      (q < 4096) { base = 0;    W = 64; }
    else if (q < 5120) { base = 4096; W = 32; }
    else if (q < 5376) { base = 5120; W = 16; }
    else               { base = 5376; W = 8;  }
    int idx = q - base;
    int ry = idx / W, rx = idx % W;
    ref[q * 2 + 0] = (rx + 0.5f) / (float)W;
    ref[q * 2 + 1] = (ry + 0.5f) / (float)W;
}

// ---------------- weight prepack: [Wv | Woff | Wattn] -> [NL,256,640] ----------------
__global__ void wcomb_kernel(const float* __restrict__ Wv,
                             const float* __restrict__ Woff,
                             const float* __restrict__ Wattn,
                             const float* __restrict__ bv,
                             const float* __restrict__ boff,
                             const float* __restrict__ battn,
                             float* __restrict__ Wc, float* __restrict__ bc)
{
    int idx = blockIdx.x * 256 + threadIdx.x;
    int total = NL_ * 256 * 640;
    if (idx < total) {
        int n = idx % 640;
        int k = (idx / 640) % 256;
        int l = idx / (640 * 256);
        float v;
        if      (n < 256) v = Wv  [((size_t)l * 256 + k) * 256 + n];
        else if (n < 512) v = Woff[((size_t)l * 256 + k) * 256 + (n - 256)];
        else              v = Wattn[((size_t)l * 256 + k) * 128 + (n - 512)];
        Wc[idx] = v;
    }
    if (idx < NL_ * 640) {
        int n = idx % 640;
        int l = idx / 640;
        float v;
        if      (n < 256) v = bv  [l * 256 + n];
        else if (n < 512) v = boff[l * 256 + (n - 256)];
        else              v = battn[l * 128 + (n - 512)];
        bc[idx] = v;
    }
}

// ---------------- mma helper ----------------
__device__ __forceinline__ void mma_tf32(float* d, const uint32_t* a, const uint32_t* b)
{
    asm volatile("mma.sync.aligned.m16n8k8.row.col.f32.tf32.tf32.f32 "
        "{%0,%1,%2,%3}, {%4,%5,%6,%7}, {%8,%9}, {%0,%1,%2,%3};"
        : "+f"(d[0]), "+f"(d[1]), "+f"(d[2]), "+f"(d[3])
        : "r"(a[0]), "r"(a[1]), "r"(a[2]), "r"(a[3]), "r"(b[0]), "r"(b[1]));
}

// ---------------- tf32 tensor-core GEMM ----------------
// C[M,N] = (A (+A2 if blockIdx.x>=bn_split)) @ W + bias, optional relu.
// BM=128 BN=128 BK=16, 8 warps. A SMEM fragment-packed (LDS.128/frag); B plain.
#define SMB 136
template<int DO_RELU, int HAS_ADD>
__global__ void __launch_bounds__(256, 2) tgemm_kernel(
    const float* __restrict__ A, const float* __restrict__ A2,
    const float* __restrict__ W, const float* __restrict__ bias,
    float* __restrict__ C, int N, int K, int bn_split)
{
    __shared__ uint32_t As[2][2112];
    __shared__ uint32_t Bs[2][16][SMB];

    int tid  = threadIdx.x;
    int lane = tid & 31;
    int wrp  = tid >> 5;
    int g    = lane >> 2;
    int tg   = lane & 3;

    int bm = blockIdx.y * 128;
    int bn = blockIdx.x * 128;
    int wm = (wrp >> 2) * 64;
    int wn = (wrp & 3) * 32;

    bool do_add = HAS_ADD && ((int)blockIdx.x >= bn_split);

    int mloc = tid >> 2;
    int kq   = tid & 3;
    int kloc = tid >> 5;
    int nloc = (tid & 31) * 4;

    const float* Ap0  = A + (size_t)(bm + mloc) * K + kq * 4;
    const float* Ap1  = Ap0 + (size_t)64 * K;
    const float* A2p0 = HAS_ADD ? (A2 + (size_t)(bm + mloc) * K + kq * 4) : nullptr;
    const float* A2p1 = HAS_ADD ? (A2p0 + (size_t)64 * K) : nullptr;
    const float* Bp0  = W + (size_t)kloc * N + bn + nloc;
    const float* Bp1  = Bp0 + (size_t)8 * N;

    int kg = kq >> 1, uk = kq & 1;
    int st0, st1;
    {
        int mgrp = mloc >> 4, p = mloc & 7, mh = (mloc >> 3) & 1;
        st0 = (kg * 264 + mgrp * 8 + p) * 4 + uk * 2 + mh;
        int m2 = mloc + 64;
        int mgrp2 = m2 >> 4, p2 = m2 & 7, mh2 = (m2 >> 3) & 1;
        st1 = (kg * 264 + mgrp2 * 8 + p2) * 4 + uk * 2 + mh2;
    }

    float acc[4][4][4];
    #pragma unroll
    for (int i = 0; i < 4; i++)
        #pragma unroll
        for (int j = 0; j < 4; j++)
            #pragma unroll
            for (int r = 0; r < 4; r++) acc[i][j][r] = 0.0f;

    int NIT = K >> 4;

    float4 va0, va1, vb0, vb1;

    va0 = *(const float4*)(Ap0);
    va1 = *(const float4*)(Ap1);
    if (do_add) {
        float4 x0 = *(const float4*)(A2p0);
        float4 x1 = *(const float4*)(A2p1);
        va0.x += x0.x; va0.y += x0.y; va0.z += x0.z; va0.w += x0.w;
        va1.x += x1.x; va1.y += x1.y; va1.z += x1.z; va1.w += x1.w;
    }
    vb0 = *(const float4*)(Bp0);
    vb1 = *(const float4*)(Bp1);

    {
        uint32_t* s = &As[0][0];
        s[st0 +   0] = __float_as_uint(va0.x);
        s[st0 + 264] = __float_as_uint(va0.y);
        s[st0 + 528] = __float_as_uint(va0.z);
        s[st0 + 792] = __float_as_uint(va0.w);
        s[st1 +   0] = __float_as_uint(va1.x);
        s[st1 + 264] = __float_as_uint(va1.y);
        s[st1 + 528] = __float_as_uint(va1.z);
        s[st1 + 792] = __float_as_uint(va1.w);
        *(float4*)&Bs[0][kloc][nloc]     = vb0;
        *(float4*)&Bs[0][kloc + 8][nloc] = vb1;
    }
    __syncthreads();

    for (int it = 0; it < NIT; it++) {
        int cur = it & 1;
        if (it + 1 < NIT) {
            int k0 = (it + 1) << 4;
            va0 = *(const float4*)(Ap0 + k0);
            va1 = *(const float4*)(Ap1 + k0);
            if (do_add) {
                float4 x0 = *(const float4*)(A2p0 + k0);
                float4 x1 = *(const float4*)(A2p1 + k0);
                va0.x += x0.x; va0.y += x0.y; va0.z += x0.z; va0.w += x0.w;
                va1.x += x1.x; va1.y += x1.y; va1.z += x1.z; va1.w += x1.w;
            }
            vb0 = *(const float4*)(Bp0 + (size_t)k0 * N);
            vb1 = *(const float4*)(Bp1 + (size_t)k0 * N);
        }

        #pragma unroll
        for (int ksg = 0; ksg < 2; ksg++) {
            const uint4* abase = (const uint4*)&As[cur][(ksg * 264 + tg * 66) * 4];
            int mgb = (wm >> 4) * 8 + g;
            uint32_t a[4][4];
            #pragma unroll
            for (int mt = 0; mt < 4; mt++) {
                uint4 v = abase[mgb + mt * 8];
                a[mt][0] = v.x; a[mt][1] = v.y; a[mt][2] = v.z; a[mt][3] = v.w;
            }
            int ks = ksg * 8;
            uint32_t b[4][2];
            #pragma unroll
            for (int nt = 0; nt < 4; nt++) {
                int nb = wn + nt * 8 + g;
                b[nt][0] = Bs[cur][ks + tg][nb];
                b[nt][1] = Bs[cur][ks + tg + 4][nb];
            }
            #pragma unroll
            for (int mt = 0; mt < 4; mt++)
                #pragma unroll
                for (int nt = 0; nt < 4; nt++)
                    mma_tf32(acc[mt][nt], a[mt], b[nt]);
        }

        if (it + 1 < NIT) {
            int nxt = (it + 1) & 1;
            __syncthreads();
            uint32_t* s = &As[nxt][0];
            s[st0 +   0] = __float_as_uint(va0.x);
            s[st0 + 264] = __float_as_uint(va0.y);
            s[st0 + 528] = __float_as_uint(va0.z);
            s[st0 + 792] = __float_as_uint(va0.w);
            s[st1 +   0] = __float_as_uint(va1.x);
            s[st1 + 264] = __float_as_uint(va1.y);
            s[st1 + 528] = __float_as_uint(va1.z);
            s[st1 + 792] = __float_as_uint(va1.w);
            *(float4*)&Bs[nxt][kloc][nloc]     = vb0;
            *(float4*)&Bs[nxt][kloc + 8][nloc] = vb1;
            __syncthreads();
        }
    }

    #pragma unroll
    for (int nt = 0; nt < 4; nt++) {
        int n = bn + wn + nt * 8 + 2 * tg;
        float b0 = bias[n], b1 = bias[n + 1];
        #pragma unroll
        for (int mt = 0; mt < 4; mt++) {
            int m0 = bm + wm + mt * 16 + g;
            float2 lo = {acc[mt][nt][0] + b0, acc[mt][nt][1] + b1};
            float2 hi = {acc[mt][nt][2] + b0, acc[mt][nt][3] + b1};
            if (DO_RELU) {
                lo.x = fmaxf(lo.x, 0.f); lo.y = fmaxf(lo.y, 0.f);
                hi.x = fmaxf(hi.x, 0.f); hi.y = fmaxf(hi.y, 0.f);
            }
            *(float2*)(C + (size_t)m0 * N + n)       = lo;
            *(float2*)(C + (size_t)(m0 + 8) * N + n) = hi;
        }
    }
}

// ---------------- LayerNorm with fused residual: out = LN(x + r) ----------------
__global__ void __launch_bounds__(256) ln_kernel(
    const float* __restrict__ x, const float* __restrict__ r,
    const float* __restrict__ g, const float* __restrict__ bta,
    float* __restrict__ out)
{
    int row = blockIdx.x;
    int d = threadIdx.x;
    size_t idx = (size_t)row * D_ + d;
    float v = x[idx] + r[idx];

    __shared__ float sh[8];
    float s = v;
    #pragma unroll
    for (int o = 16; o; o >>= 1) s += __shfl_xor_sync(0xffffffffu, s, o);
    if ((d & 31) == 0) sh[d >> 5] = s;
    __syncthreads();
    float mean = (sh[0]+sh[1]+sh[2]+sh[3]+sh[4]+sh[5]+sh[6]+sh[7]) * (1.0f / D_);
    __syncthreads();

    float c = v - mean;
    float s2 = c * c;
    #pragma unroll
    for (int o = 16; o; o >>= 1) s2 += __shfl_xor_sync(0xffffffffu, s2, o);
    if ((d & 31) == 0) sh[d >> 5] = s2;
    __syncthreads();
    float var = (sh[0]+sh[1]+sh[2]+sh[3]+sh[4]+sh[5]+sh[6]+sh[7]) * (1.0f / D_);

    out[idx] = c * rsqrtf(var + 1e-5f) * g[d] + bta[d];
}

// ---------------- deformable attention (one warp per (b,q,h)) ----------------
// voa rows stride 640: [v(256) | off(256) | logits(128)]
__global__ void __launch_bounds__(256) deform_kernel(
    const float* __restrict__ voa,
    const float* __restrict__ ref,
    float* __restrict__ out)
{
    const int dims [4] = {64, 32, 16, 8};
    const int bases[4] = {0, 4096, 5120, 5376};

    int bq   = blockIdx.x;
    int h    = threadIdx.x >> 5;
    int lane = threadIdx.x & 31;
    int b = bq / LQ_;
    int q = bq % LQ_;

    const float* lg = voa + (size_t)bq * 640 + 512 + h * 16;
    float xv = (lane < 16) ? lg[lane] : -1e30f;
    float m = xv;
    #pragma unroll
    for (int o = 8; o; o >>= 1) m = fmaxf(m, __shfl_xor_sync(0xffffffffu, m, o));
    float e = (lane < 16) ? __expf(xv - m) : 0.0f;
    float s = e;
    #pragma unroll
    for (int o = 8; o; o >>= 1) s += __shfl_xor_sync(0xffffffffu, s, o);
    float aw = e / s;

    float offv = voa[(size_t)bq * 640 + 256 + h * 32 + lane];
    float refx = ref[q * 2 + 0];
    float refy = ref[q * 2 + 1];

    const float* vb = voa + (size_t)b * LQ_ * 640 + h * HD_ + lane;

    float acc = 0.0f;
    #pragma unroll
    for (int l = 0; l < 4; l++) {
        const int Wl = dims[l];
        const int base = bases[l];
        const float Wf = (float)Wl;
        #pragma unroll
        for (int p = 0; p < 4; p++) {
            int pt = l * 4 + p;
            float ax = __shfl_sync(0xffffffffu, offv, pt * 2 + 0);
            float ay = __shfl_sync(0xffffffffu, offv, pt * 2 + 1);
            float a  = __shfl_sync(0xffffffffu, aw, pt);
            float xf = refx * Wf + ax - 0.5f;
            float yf = refy * Wf + ay - 0.5f;
            float x0f = floorf(xf), y0f = floorf(yf);
            float wx = xf - x0f,   wy = yf - y0f;
            int x0 = (int)x0f, y0 = (int)y0f;
            int x1 = x0 + 1,   y1 = y0 + 1;

            float w00 = (1.f - wy) * (1.f - wx);
            float w01 = (1.f - wy) * wx;
            float w10 = wy * (1.f - wx);
            float w11 = wy * wx;

            if (y0 >= 0 && y0 < Wl) {
                if (x0 >= 0 && x0 < Wl)
                    acc = fmaf(a * w00, vb[(size_t)(base + y0 * Wl + x0) * 640], acc);
                if (x1 >= 0 && x1 < Wl)
                    acc = fmaf(a * w01, vb[(size_t)(base + y0 * Wl + x1) * 640], acc);
            }
            if (y1 >= 0 && y1 < Wl) {
                if (x0 >= 0 && x0 < Wl)
                    acc = fmaf(a * w10, vb[(size_t)(base + y1 * Wl + x0) * 640], acc);
                if (x1 >= 0 && x1 < Wl)
                    acc = fmaf(a * w11, vb[(size_t)(base + y1 * Wl + x1) * 640], acc);
            }
        }
    }
    out[(size_t)bq * 256 + h * HD_ + lane] = acc;
}

// ---------------- host orchestration ----------------
static float* sym_ptr(const void* sym)
{
    void* p = nullptr;
    cudaGetSymbolAddress(&p, sym);
    return (float*)p;
}

extern "C" void kernel_launch(void* const* d_in, const int* in_sizes, int n_in,
                              void* d_out, int out_size)
{
    bool interleaved = (in_sizes[1] == in_sizes[0]);
    const float* srcs[4];
    const float* poss[4];
    for (int l = 0; l < 4; l++) {
        srcs[l] = (const float*)d_in[interleaved ? 2 * l     : l];
        poss[l] = (const float*)d_in[interleaved ? 2 * l + 1 : 4 + l];
    }
    const float* level_embed = (const float*)d_in[8];
    const float* W_off  = (const float*)d_in[9];
    const float* b_off  = (const float*)d_in[10];
    const float* W_attn = (const float*)d_in[11];
    const float* b_attn = (const float*)d_in[12];
    const float* W_v    = (const float*)d_in[13];
    const float* b_v    = (const float*)d_in[14];
    const float* W_o    = (const float*)d_in[15];
    const float* b_o    = (const float*)d_in[16];
    const float* ln1_g  = (const float*)d_in[17];
    const float* ln1_b  = (const float*)d_in[18];
    const float* W_fc1  = (const float*)d_in[19];
    const float* b_fc1  = (const float*)d_in[20];
    const float* W_fc2  = (const float*)d_in[21];
    const float* b_fc2  = (const float*)d_in[22];
    const float* ln2_g  = (const float*)d_in[23];
    const float* ln2_b  = (const float*)d_in[24];

    float* pos  = sym_ptr(g_pos);
    float* out  = sym_ptr(g_out);
    float* voa  = sym_ptr(g_voa);
    float* defo = sym_ptr(g_def);
    float* tmp  = sym_ptr(g_tmp);
    float* ffn  = sym_ptr(g_ffn);
    float* ref  = sym_ptr(g_ref);
    float* wc   = sym_ptr(g_wc);
    float* bc   = sym_ptr(g_bc);

    dim3 tb(32, 8);
    flatten_all_kernel<<<dim3(170, D_ / 32, B_), tb>>>(
        srcs[0], srcs[1], srcs[2], srcs[3],
        poss[0], poss[1], poss[2], poss[3],
        level_embed, out, pos);
    ref_kernel<<<(LQ_ + 255) / 256, 256>>>(ref);
    wcomb_kernel<<<(NL_ * 256 * 640 + 255) / 256, 256>>>(
        W_v, W_off, W_attn, b_v, b_off, b_attn, wc, bc);

    const int MB = MROWS / 128; // 170
    for (int i = 0; i < NL_; i++) {
        const float* Wc  = wc    + (size_t)i * 256 * 640;
        const float* Bc  = bc    + (size_t)i * 640;
        const float* Wo  = W_o   + (size_t)i * D_ * D_;
        const float* bo  = b_o   + (size_t)i * D_;
        const float* Wf1 = W_fc1 + (size_t)i * D_ * FF_;
        const float* bf1 = b_fc1 + (size_t)i * FF_;
        const float* Wf2 = W_fc2 + (size_t)i * FF_ * D_;
        const float* bf2 = b_fc2 + (size_t)i * D_;

        // fused V | off | attn GEMM: bn<2 -> no pos add (V), bn>=2 -> +pos
        tgemm_kernel<0,1><<<dim3(5, MB), 256>>>(out, pos, Wc, Bc, voa, 640, 256, 2);

        deform_kernel<<<MROWS, 256>>>(voa, ref, defo);

        tgemm_kernel<0,0><<<dim3(2, MB), 256>>>(defo, nullptr, Wo, bo, tmp, 256, 256, 0);
        ln_kernel<<<MROWS, 256>>>(out, tmp, ln1_g + i * D_, ln1_b + i * D_, out);

        tgemm_kernel<1,0><<<dim3(8, MB), 256>>>(out, nullptr, Wf1, bf1, ffn, 1024, 256, 0);
        tgemm_kernel<0,0><<<dim3(2, MB), 256>>>(ffn, nullptr, Wf2, bf2, tmp, 256, 1024, 0);

        float* lnout = (i == NL_ - 1) ? (float*)d_out : out;
        ln_kernel<<<MROWS, 256>>>(out, tmp, ln2_g + i * D_, ln2_b + i * D_, lnout);
    }
}

// round 7
// speedup vs baseline: 2.7294x; 1.1143x over previous
#include <cuda_runtime.h>
#include <math.h>
#include <stdint.h>

#define B_  4
#define LQ_ 5440
#define D_  256
#define H_  8
#define HD_ 32
#define FF_ 1024
#define NL_ 6
#define MROWS (B_*LQ_)   // 21760

// ---------------- scratch (device globals; no allocation) ----------------
__device__ float g_pos [MROWS*D_];
__device__ float g_out [MROWS*D_];
__device__ float g_qpos[MROWS*D_];
__device__ float g_voa [MROWS*640];   // fused [v(256) | off(256) | logits(128)]
__device__ float g_def [MROWS*D_];
__device__ float g_tmp [MROWS*D_];
__device__ float g_ffn [MROWS*FF_];
__device__ float g_ref [LQ_*2];
__device__ float g_wt_voa[NL_*640*256];   // [N,K] transposed [Wv|Woff|Wattn]
__device__ float g_wt_o  [NL_*256*256];
__device__ float g_wt_f1 [NL_*1024*256];
__device__ float g_wt_f2 [NL_*256*1024];
__device__ float g_bc    [NL_*640];

// ---------------- fused flatten: all 4 levels, src+pos, + qpos ----------------
__global__ void flatten_all_kernel(
    const float* __restrict__ s0, const float* __restrict__ s1,
    const float* __restrict__ s2, const float* __restrict__ s3,
    const float* __restrict__ p0, const float* __restrict__ p1,
    const float* __restrict__ p2, const float* __restrict__ p3,
    const float* __restrict__ lvl_emb,
    float* __restrict__ dsrc, float* __restrict__ dpos, float* __restrict__ dqpos)
{
    __shared__ float ts[32][33];
    __shared__ float tp[32][33];

    int t = blockIdx.x;
    int level, hwt, HW, base;
    if      (t < 128) { level = 0; hwt = t;       HW = 4096; base = 0;    }
    else if (t < 160) { level = 1; hwt = t - 128; HW = 1024; base = 4096; }
    else if (t < 168) { level = 2; hwt = t - 160; HW = 256;  base = 5120; }
    else              { level = 3; hwt = t - 168; HW = 64;   base = 5376; }

    const float* src = (level == 0) ? s0 : (level == 1) ? s1 : (level == 2) ? s2 : s3;
    const float* pos = (level == 0) ? p0 : (level == 1) ? p1 : (level == 2) ? p2 : p3;

    int b  = blockIdx.z;
    int tx = threadIdx.x, ty = threadIdx.y;
    int hw0 = hwt * 32;
    int d0  = blockIdx.y * 32;

    const float* sp = src + ((size_t)b * D_) * HW;
    const float* pp = pos + ((size_t)b * D_) * HW;
    #pragma unroll
    for (int j = 0; j < 32; j += 8) {
        ts[ty + j][tx] = sp[(size_t)(d0 + ty + j) * HW + hw0 + tx];
        tp[ty + j][tx] = pp[(size_t)(d0 + ty + j) * HW + hw0 + tx];
    }
    __syncthreads();
    float add = lvl_emb[level * D_ + d0 + tx];
    #pragma unroll
    for (int j = 0; j < 32; j += 8) {
        int hw = hw0 + ty + j;
        size_t row = ((size_t)b * LQ_ + base + hw) * D_ + d0 + tx;
        float sv = ts[tx][ty + j];
        float pv = tp[tx][ty + j] + add;
        dsrc[row]  = sv;
        dpos[row]  = pv;
        dqpos[row] = sv + pv;
    }
}

// ---------------- reference points ----------------
__global__ void ref_kernel(float* __restrict__ ref)
{
    int q = blockIdx.x * 256 + threadIdx.x;
    if (q >= LQ_) return;
    int base, W;
    if      (q < 4096) { base = 0;    W = 64; }
    else if (q < 5120) { base = 4096; W = 32; }
    else if (q < 5376) { base = 5120; W = 16; }
    else               { base = 5376; W = 8;  }
    int idx = q - base;
    int ry = idx / W, rx = idx % W;
    ref[q * 2 + 0] = (rx + 0.5f) / (float)W;
    ref[q * 2 + 1] = (ry + 0.5f) / (float)W;
}

// ---------------- weight transpose: [K,N] -> [N,K], per-layer strides ----------------
__global__ void wtrans_kernel(const float* __restrict__ src, float* __restrict__ dst,
                              int K, int N, size_t src_l, size_t dst_l)
{
    __shared__ float t[32][33];
    int l = blockIdx.z;
    int n0 = blockIdx.x * 32, k0 = blockIdx.y * 32;
    int tx = threadIdx.x, ty = threadIdx.y;
    const float* s = src + (size_t)l * src_l;
    float* d = dst + (size_t)l * dst_l;
    #pragma unroll
    for (int j = 0; j < 32; j += 8)
        t[ty + j][tx] = s[(size_t)(k0 + ty + j) * N + n0 + tx];
    __syncthreads();
    #pragma unroll
    for (int j = 0; j < 32; j += 8)
        d[(size_t)(n0 + ty + j) * K + k0 + tx] = t[tx][ty + j];
}

// ---------------- bias combine for voa ----------------
__global__ void bcomb_kernel(const float* __restrict__ bv,
                             const float* __restrict__ boff,
                             const float* __restrict__ battn,
                             float* __restrict__ bc)
{
    int idx = blockIdx.x * 256 + threadIdx.x;
    if (idx >= NL_ * 640) return;
    int n = idx % 640;
    int l = idx / 640;
    float v;
    if      (n < 256) v = bv  [l * 256 + n];
    else if (n < 512) v = boff[l * 256 + (n - 256)];
    else              v = battn[l * 128 + (n - 512)];
    bc[idx] = v;
}

// ---------------- asm helpers ----------------
__device__ __forceinline__ void mma_tf32(float* d, const uint32_t* a, const uint32_t* b)
{
    asm volatile("mma.sync.aligned.m16n8k8.row.col.f32.tf32.tf32.f32 "
        "{%0,%1,%2,%3}, {%4,%5,%6,%7}, {%8,%9}, {%0,%1,%2,%3};"
        : "+f"(d[0]), "+f"(d[1]), "+f"(d[2]), "+f"(d[3])
        : "r"(a[0]), "r"(a[1]), "r"(a[2]), "r"(a[3]), "r"(b[0]), "r"(b[1]));
}
__device__ __forceinline__ void ldsm4(uint32_t* r, uint32_t addr)
{
    asm volatile("ldmatrix.sync.aligned.m8n8.x4.shared.b16 {%0,%1,%2,%3}, [%4];"
        : "=r"(r[0]), "=r"(r[1]), "=r"(r[2]), "=r"(r[3]) : "r"(addr));
}
__device__ __forceinline__ void cpa16(uint32_t dst, const void* src)
{
    asm volatile("cp.async.cg.shared.global [%0], [%1], 16;" :: "r"(dst), "l"(src));
}
#define CP_COMMIT() asm volatile("cp.async.commit_group;" ::: "memory")
#define CP_WAIT2()  asm volatile("cp.async.wait_group 2;" ::: "memory")

// ---------------- tf32 GEMM: cp.async 4-stage + ldmatrix ----------------
// C[M,N] = A @ Wt^T + bias. A [M,K] fp32 row-major; Wt [N,K] fp32 row-major.
// A = (blockIdx.x < bn_split) ? A0 : A1. BM=128 BN=128 BK=16, 256 thr, 8 warps.
// SMEM per stage: A 128 rows x 80B (64B data + 16B pad), B same. 4 stages = 80KB.
#define STG_BYTES 20480
#define GEMM_SMEM (4*STG_BYTES)
template<int DO_RELU>
__global__ void __launch_bounds__(256, 2) tgemm_kernel(
    const float* __restrict__ A0, const float* __restrict__ A1,
    const float* __restrict__ Wt, const float* __restrict__ bias,
    float* __restrict__ C, int N, int K, int bn_split)
{
    extern __shared__ char smc[];
    uint32_t smb = (uint32_t)__cvta_generic_to_shared(smc);

    int tid  = threadIdx.x;
    int lane = tid & 31;
    int wrp  = tid >> 5;
    int g    = lane >> 2;
    int tg   = lane & 3;

    int bm = blockIdx.y * 128;
    int bn = blockIdx.x * 128;
    int wm = (wrp >> 2) * 64;
    int wn = (wrp & 3) * 32;

    const float* A = ((int)blockIdx.x < bn_split) ? A0 : A1;

    // loader: 2 chunks each for A and B per stage per thread
    int r0l = (tid + 0)   >> 2, c0l = (tid + 0)   & 3;
    int r1l = (tid + 256) >> 2, c1l = (tid + 256) & 3;
    const float* gA0 = A  + (size_t)(bm + r0l) * K + c0l * 4;
    const float* gA1 = A  + (size_t)(bm + r1l) * K + c1l * 4;
    const float* gB0 = Wt + (size_t)(bn + r0l) * K + c0l * 4;
    const float* gB1 = Wt + (size_t)(bn + r1l) * K + c1l * 4;
    uint32_t dA0 = r0l * 80 + c0l * 16;
    uint32_t dA1 = r1l * 80 + c1l * 16;

    // ldmatrix per-lane offsets
    uint32_t a_off = (uint32_t)((lane & 15) * 80 + ((lane & 16) ? 16 : 0));
    uint32_t b_off = (uint32_t)(((lane & 7) + ((lane & 16) ? 8 : 0)) * 80 + ((lane & 8) ? 16 : 0));

    float acc[4][4][4];
    #pragma unroll
    for (int i = 0; i < 4; i++)
        #pragma unroll
        for (int j = 0; j < 4; j++)
            #pragma unroll
            for (int r = 0; r < 4; r++) acc[i][j][r] = 0.0f;

    int NIT = K >> 4;

    // prologue: stages 0..2
    #pragma unroll
    for (int s = 0; s < 3; s++) {
        int k0 = s << 4;
        uint32_t sb = smb + s * STG_BYTES;
        cpa16(sb + dA0,         gA0 + k0);
        cpa16(sb + dA1,         gA1 + k0);
        cpa16(sb + 10240 + dA0, gB0 + k0);
        cpa16(sb + 10240 + dA1, gB1 + k0);
        CP_COMMIT();
    }

    for (int it = 0; it < NIT; it++) {
        CP_WAIT2();
        __syncthreads();

        if (it + 3 < NIT) {
            int s = (it + 3) & 3;
            int k0 = (it + 3) << 4;
            uint32_t sb = smb + s * STG_BYTES;
            cpa16(sb + dA0,         gA0 + k0);
            cpa16(sb + dA1,         gA1 + k0);
            cpa16(sb + 10240 + dA0, gB0 + k0);
            cpa16(sb + 10240 + dA1, gB1 + k0);
        }
        CP_COMMIT();

        uint32_t sb = smb + (it & 3) * STG_BYTES;
        uint32_t abase = sb + wm * 80 + a_off;
        uint32_t bbase = sb + 10240 + wn * 80 + b_off;

        #pragma unroll
        for (int ksg = 0; ksg < 2; ksg++) {
            uint32_t a[4][4];
            #pragma unroll
            for (int mt = 0; mt < 4; mt++)
                ldsm4(a[mt], abase + mt * 16 * 80 + ksg * 32);
            uint32_t b[4][2];
            #pragma unroll
            for (int ntp = 0; ntp < 2; ntp++) {
                uint32_t r[4];
                ldsm4(r, bbase + ntp * 16 * 80 + ksg * 32);
                b[2 * ntp + 0][0] = r[0]; b[2 * ntp + 0][1] = r[1];
                b[2 * ntp + 1][0] = r[2]; b[2 * ntp + 1][1] = r[3];
            }
            #pragma unroll
            for (int mt = 0; mt < 4; mt++)
                #pragma unroll
                for (int nt = 0; nt < 4; nt++)
                    mma_tf32(acc[mt][nt], a[mt], b[nt]);
        }
    }

    // epilogue: bias (+relu), fp32 out
    #pragma unroll
    for (int nt = 0; nt < 4; nt++) {
        int n = bn + wn + nt * 8 + 2 * tg;
        float b0 = bias[n], b1 = bias[n + 1];
        #pragma unroll
        for (int mt = 0; mt < 4; mt++) {
            int m0 = bm + wm + mt * 16 + g;
            float2 lo = {acc[mt][nt][0] + b0, acc[mt][nt][1] + b1};
            float2 hi = {acc[mt][nt][2] + b0, acc[mt][nt][3] + b1};
            if (DO_RELU) {
                lo.x = fmaxf(lo.x, 0.f); lo.y = fmaxf(lo.y, 0.f);
                hi.x = fmaxf(hi.x, 0.f); hi.y = fmaxf(hi.y, 0.f);
            }
            *(float2*)(C + (size_t)m0 * N + n)       = lo;
            *(float2*)(C + (size_t)(m0 + 8) * N + n) = hi;
        }
    }
}

// ---------------- LayerNorm fused residual (+ optional qpos out) ----------------
__global__ void __launch_bounds__(256) ln_kernel(
    const float* __restrict__ x, const float* __restrict__ r,
    const float* __restrict__ g, const float* __restrict__ bta,
    float* __restrict__ out,
    const float* __restrict__ pos, float* __restrict__ qpos)
{
    int row = blockIdx.x;
    int d = threadIdx.x;
    size_t idx = (size_t)row * D_ + d;
    float v = x[idx] + r[idx];

    __shared__ float sh[8];
    float s = v;
    #pragma unroll
    for (int o = 16; o; o >>= 1) s += __shfl_xor_sync(0xffffffffu, s, o);
    if ((d & 31) == 0) sh[d >> 5] = s;
    __syncthreads();
    float mean = (sh[0]+sh[1]+sh[2]+sh[3]+sh[4]+sh[5]+sh[6]+sh[7]) * (1.0f / D_);
    __syncthreads();

    float c = v - mean;
    float s2 = c * c;
    #pragma unroll
    for (int o = 16; o; o >>= 1) s2 += __shfl_xor_sync(0xffffffffu, s2, o);
    if ((d & 31) == 0) sh[d >> 5] = s2;
    __syncthreads();
    float var = (sh[0]+sh[1]+sh[2]+sh[3]+sh[4]+sh[5]+sh[6]+sh[7]) * (1.0f / D_);

    float o = c * rsqrtf(var + 1e-5f) * g[d] + bta[d];
    out[idx] = o;
    if (qpos) qpos[idx] = o + pos[idx];
}

// ---------------- deformable attention (one warp per (b,q,h)) ----------------
__global__ void __launch_bounds__(256) deform_kernel(
    const float* __restrict__ voa,
    const float* __restrict__ ref,
    float* __restrict__ out)
{
    const int dims [4] = {64, 32, 16, 8};
    const int bases[4] = {0, 4096, 5120, 5376};

    int bq   = blockIdx.x;
    int h    = threadIdx.x >> 5;
    int lane = threadIdx.x & 31;
    int b = bq / LQ_;
    int q = bq % LQ_;

    const float* lg = voa + (size_t)bq * 640 + 512 + h * 16;
    float xv = (lane < 16) ? lg[lane] : -1e30f;
    float m = xv;
    #pragma unroll
    for (int o = 8; o; o >>= 1) m = fmaxf(m, __shfl_xor_sync(0xffffffffu, m, o));
    float e = (lane < 16) ? __expf(xv - m) : 0.0f;
    float s = e;
    #pragma unroll
    for (int o = 8; o; o >>= 1) s += __shfl_xor_sync(0xffffffffu, s, o);
    float aw = e / s;

    float offv = voa[(size_t)bq * 640 + 256 + h * 32 + lane];
    float refx = ref[q * 2 + 0];
    float refy = ref[q * 2 + 1];

    const float* vb = voa + (size_t)b * LQ_ * 640 + h * HD_ + lane;

    float acc = 0.0f;
    #pragma unroll
    for (int l = 0; l < 4; l++) {
        const int Wl = dims[l];
        const int base = bases[l];
        const float Wf = (float)Wl;
        #pragma unroll
        for (int p = 0; p < 4; p++) {
            int pt = l * 4 + p;
            float ax = __shfl_sync(0xffffffffu, offv, pt * 2 + 0);
            float ay = __shfl_sync(0xffffffffu, offv, pt * 2 + 1);
            float a  = __shfl_sync(0xffffffffu, aw, pt);
            float xf = refx * Wf + ax - 0.5f;
            float yf = refy * Wf + ay - 0.5f;
            float x0f = floorf(xf), y0f = floorf(yf);
            float wx = xf - x0f,   wy = yf - y0f;
            int x0 = (int)x0f, y0 = (int)y0f;
            int x1 = x0 + 1,   y1 = y0 + 1;

            float w00 = (1.f - wy) * (1.f - wx);
            float w01 = (1.f - wy) * wx;
            float w10 = wy * (1.f - wx);
            float w11 = wy * wx;

            if (y0 >= 0 && y0 < Wl) {
                if (x0 >= 0 && x0 < Wl)
                    acc = fmaf(a * w00, vb[(size_t)(base + y0 * Wl + x0) * 640], acc);
                if (x1 >= 0 && x1 < Wl)
                    acc = fmaf(a * w01, vb[(size_t)(base + y0 * Wl + x1) * 640], acc);
            }
            if (y1 >= 0 && y1 < Wl) {
                if (x0 >= 0 && x0 < Wl)
                    acc = fmaf(a * w10, vb[(size_t)(base + y1 * Wl + x0) * 640], acc);
                if (x1 >= 0 && x1 < Wl)
                    acc = fmaf(a * w11, vb[(size_t)(base + y1 * Wl + x1) * 640], acc);
            }
        }
    }
    out[(size_t)bq * 256 + h * HD_ + lane] = acc;
}

// ---------------- host orchestration ----------------
static float* sym_ptr(const void* sym)
{
    void* p = nullptr;
    cudaGetSymbolAddress(&p, sym);
    return (float*)p;
}

extern "C" void kernel_launch(void* const* d_in, const int* in_sizes, int n_in,
                              void* d_out, int out_size)
{
    bool interleaved = (in_sizes[1] == in_sizes[0]);
    const float* srcs[4];
    const float* poss[4];
    for (int l = 0; l < 4; l++) {
        srcs[l] = (const float*)d_in[interleaved ? 2 * l     : l];
        poss[l] = (const float*)d_in[interleaved ? 2 * l + 1 : 4 + l];
    }
    const float* level_embed = (const float*)d_in[8];
    const float* W_off  = (const float*)d_in[9];
    const float* b_off  = (const float*)d_in[10];
    const float* W_attn = (const float*)d_in[11];
    const float* b_attn = (const float*)d_in[12];
    const float* W_v    = (const float*)d_in[13];
    const float* b_v    = (const float*)d_in[14];
    const float* W_o    = (const float*)d_in[15];
    const float* b_o    = (const float*)d_in[16];
    const float* ln1_g  = (const float*)d_in[17];
    const float* ln1_b  = (const float*)d_in[18];
    const float* W_fc1  = (const float*)d_in[19];
    const float* b_fc1  = (const float*)d_in[20];
    const float* W_fc2  = (const float*)d_in[21];
    const float* b_fc2  = (const float*)d_in[22];
    const float* ln2_g  = (const float*)d_in[23];
    const float* ln2_b  = (const float*)d_in[24];

    float* pos  = sym_ptr(g_pos);
    float* out  = sym_ptr(g_out);
    float* qpos = sym_ptr(g_qpos);
    float* voa  = sym_ptr(g_voa);
    float* defo = sym_ptr(g_def);
    float* tmp  = sym_ptr(g_tmp);
    float* ffn  = sym_ptr(g_ffn);
    float* ref  = sym_ptr(g_ref);
    float* wvoa = sym_ptr(g_wt_voa);
    float* wo   = sym_ptr(g_wt_o);
    float* wf1  = sym_ptr(g_wt_f1);
    float* wf2  = sym_ptr(g_wt_f2);
    float* bc   = sym_ptr(g_bc);

    cudaFuncSetAttribute(tgemm_kernel<0>, cudaFuncAttributeMaxDynamicSharedMemorySize, GEMM_SMEM);
    cudaFuncSetAttribute(tgemm_kernel<1>, cudaFuncAttributeMaxDynamicSharedMemorySize, GEMM_SMEM);

    dim3 tb(32, 8);
    flatten_all_kernel<<<dim3(170, D_ / 32, B_), tb>>>(
        srcs[0], srcs[1], srcs[2], srcs[3],
        poss[0], poss[1], poss[2], poss[3],
        level_embed, out, pos, qpos);
    ref_kernel<<<(LQ_ + 255) / 256, 256>>>(ref);

    // one-time weight transposes to [N,K]
    wtrans_kernel<<<dim3(8,  8,  NL_), tb>>>(W_v,    wvoa,             256, 256,  65536,  640*256);
    wtrans_kernel<<<dim3(8,  8,  NL_), tb>>>(W_off,  wvoa + 256*256,   256, 256,  65536,  640*256);
    wtrans_kernel<<<dim3(4,  8,  NL_), tb>>>(W_attn, wvoa + 512*256,   256, 128,  32768,  640*256);
    wtrans_kernel<<<dim3(8,  8,  NL_), tb>>>(W_o,    wo,               256, 256,  65536,  256*256);
    wtrans_kernel<<<dim3(32, 8,  NL_), tb>>>(W_fc1,  wf1,              256, 1024, 262144, 1024*256);
    wtrans_kernel<<<dim3(8,  32, NL_), tb>>>(W_fc2,  wf2,              1024,256,  262144, 256*1024);
    bcomb_kernel<<<(NL_ * 640 + 255) / 256, 256>>>(b_v, b_off, b_attn, bc);

    const int MB = MROWS / 128; // 170
    for (int i = 0; i < NL_; i++) {
        const float* Wvoa = wvoa  + (size_t)i * 640 * 256;
        const float* Bc   = bc    + (size_t)i * 640;
        const float* Wo   = wo    + (size_t)i * 256 * 256;
        const float* bo   = b_o   + (size_t)i * D_;
        const float* Wf1  = wf1   + (size_t)i * 1024 * 256;
        const float* bf1  = b_fc1 + (size_t)i * FF_;
        const float* Wf2  = wf2   + (size_t)i * 256 * 1024;
        const float* bf2  = b_fc2 + (size_t)i * D_;

        // fused V|off|attn GEMM: bn<2 -> A=out (V), bn>=2 -> A=qpos
        tgemm_kernel<0><<<dim3(5, MB), 256, GEMM_SMEM>>>(out, qpos, Wvoa, Bc, voa, 640, 256, 2);

        deform_kernel<<<MROWS, 256>>>(voa, ref, defo);

        tgemm_kernel<0><<<dim3(2, MB), 256, GEMM_SMEM>>>(defo, defo, Wo, bo, tmp, 256, 256, 0);
        ln_kernel<<<MROWS, 256>>>(out, tmp, ln1_g + i * D_, ln1_b + i * D_, out, nullptr, nullptr);

        tgemm_kernel<1><<<dim3(8, MB), 256, GEMM_SMEM>>>(out, out, Wf1, bf1, ffn, 1024, 256, 0);
        tgemm_kernel<0><<<dim3(2, MB), 256, GEMM_SMEM>>>(ffn, ffn, Wf2, bf2, tmp, 256, 1024, 0);

        if (i == NL_ - 1) {
            ln_kernel<<<MROWS, 256>>>(out, tmp, ln2_g + i * D_, ln2_b + i * D_,
                                      (float*)d_out, nullptr, nullptr);
        } else {
            ln_kernel<<<MROWS, 256>>>(out, tmp, ln2_g + i * D_, ln2_b + i * D_,
                                      out, pos, qpos);
        }
    }
}

// round 8
// speedup vs baseline: 2.8417x; 1.0411x over previous
#include <cuda_runtime.h>
#include <math.h>
#include <stdint.h>

#define B_  4
#define LQ_ 5440
#define D_  256
#define H_  8
#define HD_ 32
#define FF_ 1024
#define NL_ 6
#define MROWS (B_*LQ_)   // 21760

// ---------------- scratch (device globals; no allocation) ----------------
__device__ float g_pos [MROWS*D_];
__device__ float g_out [MROWS*D_];
__device__ float g_qpos[MROWS*D_];
__device__ float g_voa [MROWS*640];   // fused [v(256) | off(256) | logits(128)]
__device__ float g_def [MROWS*D_];
__device__ float g_ffn [MROWS*FF_];
__device__ float g_ref [LQ_*2];
__device__ float g_wt_voa[NL_*640*256];   // [N,K] transposed [Wv|Woff|Wattn]
__device__ float g_wt_o  [NL_*256*256];
__device__ float g_wt_f1 [NL_*1024*256];
__device__ float g_wt_f2 [NL_*256*1024];
__device__ float g_bc    [NL_*640];

// ---------------- fused flatten: all 4 levels, src+pos, + qpos ----------------
__global__ void flatten_all_kernel(
    const float* __restrict__ s0, const float* __restrict__ s1,
    const float* __restrict__ s2, const float* __restrict__ s3,
    const float* __restrict__ p0, const float* __restrict__ p1,
    const float* __restrict__ p2, const float* __restrict__ p3,
    const float* __restrict__ lvl_emb,
    float* __restrict__ dsrc, float* __restrict__ dpos, float* __restrict__ dqpos)
{
    __shared__ float ts[32][33];
    __shared__ float tp[32][33];

    int t = blockIdx.x;
    int level, hwt, HW, base;
    if      (t < 128) { level = 0; hwt = t;       HW = 4096; base = 0;    }
    else if (t < 160) { level = 1; hwt = t - 128; HW = 1024; base = 4096; }
    else if (t < 168) { level = 2; hwt = t - 160; HW = 256;  base = 5120; }
    else              { level = 3; hwt = t - 168; HW = 64;   base = 5376; }

    const float* src = (level == 0) ? s0 : (level == 1) ? s1 : (level == 2) ? s2 : s3;
    const float* pos = (level == 0) ? p0 : (level == 1) ? p1 : (level == 2) ? p2 : p3;

    int b  = blockIdx.z;
    int tx = threadIdx.x, ty = threadIdx.y;
    int hw0 = hwt * 32;
    int d0  = blockIdx.y * 32;

    const float* sp = src + ((size_t)b * D_) * HW;
    const float* pp = pos + ((size_t)b * D_) * HW;
    #pragma unroll
    for (int j = 0; j < 32; j += 8) {
        ts[ty + j][tx] = sp[(size_t)(d0 + ty + j) * HW + hw0 + tx];
        tp[ty + j][tx] = pp[(size_t)(d0 + ty + j) * HW + hw0 + tx];
    }
    __syncthreads();
    float add = lvl_emb[level * D_ + d0 + tx];
    #pragma unroll
    for (int j = 0; j < 32; j += 8) {
        int hw = hw0 + ty + j;
        size_t row = ((size_t)b * LQ_ + base + hw) * D_ + d0 + tx;
        float sv = ts[tx][ty + j];
        float pv = tp[tx][ty + j] + add;
        dsrc[row]  = sv;
        dpos[row]  = pv;
        dqpos[row] = sv + pv;
    }
}

// ---------------- reference points ----------------
__global__ void ref_kernel(float* __restrict__ ref)
{
    int q = blockIdx.x * 256 + threadIdx.x;
    if (q >= LQ_) return;
    int base, W;
    if      (q < 4096) { base = 0;    W = 64; }
    else if (q < 5120) { base = 4096; W = 32; }
    else if (q < 5376) { base = 5120; W = 16; }
    else               { base = 5376; W = 8;  }
    int idx = q - base;
    int ry = idx / W, rx = idx % W;
    ref[q * 2 + 0] = (rx + 0.5f) / (float)W;
    ref[q * 2 + 1] = (ry + 0.5f) / (float)W;
}

// ---------------- weight transpose: [K,N] -> [N,K] ----------------
__global__ void wtrans_kernel(const float* __restrict__ src, float* __restrict__ dst,
                              int K, int N, size_t src_l, size_t dst_l)
{
    __shared__ float t[32][33];
    int l = blockIdx.z;
    int n0 = blockIdx.x * 32, k0 = blockIdx.y * 32;
    int tx = threadIdx.x, ty = threadIdx.y;
    const float* s = src + (size_t)l * src_l;
    float* d = dst + (size_t)l * dst_l;
    #pragma unroll
    for (int j = 0; j < 32; j += 8)
        t[ty + j][tx] = s[(size_t)(k0 + ty + j) * N + n0 + tx];
    __syncthreads();
    #pragma unroll
    for (int j = 0; j < 32; j += 8)
        d[(size_t)(n0 + ty + j) * K + k0 + tx] = t[tx][ty + j];
}

// ---------------- bias combine for voa ----------------
__global__ void bcomb_kernel(const float* __restrict__ bv,
                             const float* __restrict__ boff,
                             const float* __restrict__ battn,
                             float* __restrict__ bc)
{
    int idx = blockIdx.x * 256 + threadIdx.x;
    if (idx >= NL_ * 640) return;
    int n = idx % 640;
    int l = idx / 640;
    float v;
    if      (n < 256) v = bv  [l * 256 + n];
    else if (n < 512) v = boff[l * 256 + (n - 256)];
    else              v = battn[l * 128 + (n - 512)];
    bc[idx] = v;
}

// ---------------- asm helpers ----------------
__device__ __forceinline__ void mma_tf32(float* d, const uint32_t* a, const uint32_t* b)
{
    asm volatile("mma.sync.aligned.m16n8k8.row.col.f32.tf32.tf32.f32 "
        "{%0,%1,%2,%3}, {%4,%5,%6,%7}, {%8,%9}, {%0,%1,%2,%3};"
        : "+f"(d[0]), "+f"(d[1]), "+f"(d[2]), "+f"(d[3])
        : "r"(a[0]), "r"(a[1]), "r"(a[2]), "r"(a[3]), "r"(b[0]), "r"(b[1]));
}
__device__ __forceinline__ void ldsm4(uint32_t* r, uint32_t addr)
{
    asm volatile("ldmatrix.sync.aligned.m8n8.x4.shared.b16 {%0,%1,%2,%3}, [%4];"
        : "=r"(r[0]), "=r"(r[1]), "=r"(r[2]), "=r"(r[3]) : "r"(addr));
}
__device__ __forceinline__ void cpa16(uint32_t dst, const void* src)
{
    asm volatile("cp.async.cg.shared.global [%0], [%1], 16;" :: "r"(dst), "l"(src));
}
#define CP_COMMIT() asm volatile("cp.async.commit_group;" ::: "memory")
#define CP_WAIT2()  asm volatile("cp.async.wait_group 2;" ::: "memory")

// ================= GEMM A: BM=128 BN=128 (VOA, FC1) ==================
#define STG_BYTES 20480
#define GEMM_SMEM (4*STG_BYTES)
template<int DO_RELU>
__global__ void __launch_bounds__(256, 2) tgemm_kernel(
    const float* __restrict__ A0, const float* __restrict__ A1,
    const float* __restrict__ Wt, const float* __restrict__ bias,
    float* __restrict__ C, int N, int K, int bn_split)
{
    extern __shared__ char smc[];
    uint32_t smb = (uint32_t)__cvta_generic_to_shared(smc);

    int tid  = threadIdx.x;
    int lane = tid & 31;
    int wrp  = tid >> 5;
    int g    = lane >> 2;
    int tg   = lane & 3;

    int bm = blockIdx.y * 128;
    int bn = blockIdx.x * 128;
    int wm = (wrp >> 2) * 64;
    int wn = (wrp & 3) * 32;

    const float* A = ((int)blockIdx.x < bn_split) ? A0 : A1;

    int r0l = (tid + 0)   >> 2, c0l = (tid + 0)   & 3;
    int r1l = (tid + 256) >> 2, c1l = (tid + 256) & 3;
    const float* gA0 = A  + (size_t)(bm + r0l) * K + c0l * 4;
    const float* gA1 = A  + (size_t)(bm + r1l) * K + c1l * 4;
    const float* gB0 = Wt + (size_t)(bn + r0l) * K + c0l * 4;
    const float* gB1 = Wt + (size_t)(bn + r1l) * K + c1l * 4;
    uint32_t dA0 = r0l * 80 + c0l * 16;
    uint32_t dA1 = r1l * 80 + c1l * 16;

    uint32_t a_off = (uint32_t)((lane & 15) * 80 + ((lane & 16) ? 16 : 0));
    uint32_t b_off = (uint32_t)(((lane & 7) + ((lane & 16) ? 8 : 0)) * 80 + ((lane & 8) ? 16 : 0));

    float acc[4][4][4];
    #pragma unroll
    for (int i = 0; i < 4; i++)
        #pragma unroll
        for (int j = 0; j < 4; j++)
            #pragma unroll
            for (int r = 0; r < 4; r++) acc[i][j][r] = 0.0f;

    int NIT = K >> 4;

    #pragma unroll
    for (int s = 0; s < 3; s++) {
        int k0 = s << 4;
        uint32_t sb = smb + s * STG_BYTES;
        cpa16(sb + dA0,         gA0 + k0);
        cpa16(sb + dA1,         gA1 + k0);
        cpa16(sb + 10240 + dA0, gB0 + k0);
        cpa16(sb + 10240 + dA1, gB1 + k0);
        CP_COMMIT();
    }

    for (int it = 0; it < NIT; it++) {
        CP_WAIT2();
        __syncthreads();

        if (it + 3 < NIT) {
            int s = (it + 3) & 3;
            int k0 = (it + 3) << 4;
            uint32_t sb = smb + s * STG_BYTES;
            cpa16(sb + dA0,         gA0 + k0);
            cpa16(sb + dA1,         gA1 + k0);
            cpa16(sb + 10240 + dA0, gB0 + k0);
            cpa16(sb + 10240 + dA1, gB1 + k0);
        }
        CP_COMMIT();

        uint32_t sb = smb + (it & 3) * STG_BYTES;
        uint32_t abase = sb + wm * 80 + a_off;
        uint32_t bbase = sb + 10240 + wn * 80 + b_off;

        #pragma unroll
        for (int ksg = 0; ksg < 2; ksg++) {
            uint32_t a[4][4];
            #pragma unroll
            for (int mt = 0; mt < 4; mt++)
                ldsm4(a[mt], abase + mt * 16 * 80 + ksg * 32);
            uint32_t b[4][2];
            #pragma unroll
            for (int ntp = 0; ntp < 2; ntp++) {
                uint32_t r[4];
                ldsm4(r, bbase + ntp * 16 * 80 + ksg * 32);
                b[2 * ntp + 0][0] = r[0]; b[2 * ntp + 0][1] = r[1];
                b[2 * ntp + 1][0] = r[2]; b[2 * ntp + 1][1] = r[3];
            }
            #pragma unroll
            for (int mt = 0; mt < 4; mt++)
                #pragma unroll
                for (int nt = 0; nt < 4; nt++)
                    mma_tf32(acc[mt][nt], a[mt], b[nt]);
        }
    }

    #pragma unroll
    for (int nt = 0; nt < 4; nt++) {
        int n = bn + wn + nt * 8 + 2 * tg;
        float b0 = bias[n], b1 = bias[n + 1];
        #pragma unroll
        for (int mt = 0; mt < 4; mt++) {
            int m0 = bm + wm + mt * 16 + g;
            float2 lo = {acc[mt][nt][0] + b0, acc[mt][nt][1] + b1};
            float2 hi = {acc[mt][nt][2] + b0, acc[mt][nt][3] + b1};
            if (DO_RELU) {
                lo.x = fmaxf(lo.x, 0.f); lo.y = fmaxf(lo.y, 0.f);
                hi.x = fmaxf(hi.x, 0.f); hi.y = fmaxf(hi.y, 0.f);
            }
            *(float2*)(C + (size_t)m0 * N + n)       = lo;
            *(float2*)(C + (size_t)(m0 + 8) * N + n) = hi;
        }
    }
}

// ========== GEMM B: BM=64 BN=256(=D), LN-fused epilogue (O-proj, FC2) ==========
// out = LN(X + A@Wt^T + bias); optional qpos = out + pos.
// 8 warps: 2 m-warps (32 rows) x 4 n-warps (64 cols). Stage: A 64*80 + B 256*80.
#define LSTG_BYTES 25600
#define LGEMM_SMEM (4*LSTG_BYTES)
__global__ void __launch_bounds__(256, 2) tgemm_ln_kernel(
    const float* __restrict__ A, const float* __restrict__ Wt,
    const float* __restrict__ bias, const float* __restrict__ X,
    const float* __restrict__ gma, const float* __restrict__ bta,
    float* __restrict__ OUT, const float* __restrict__ pos,
    float* __restrict__ qpos, int K)
{
    extern __shared__ char smc[];
    uint32_t smb = (uint32_t)__cvta_generic_to_shared(smc);
    __shared__ float red[64][4][2];

    int tid  = threadIdx.x;
    int lane = tid & 31;
    int wrp  = tid >> 5;
    int g    = lane >> 2;
    int tg   = lane & 3;

    int bm = blockIdx.x * 64;
    int wml = (wrp >> 2) * 32;          // warp m offset (local)
    int wn  = (wrp & 3) * 64;           // warp n offset

    // loaders: A 1 chunk/thread, B 4 chunks/thread
    int ra = tid >> 2, ca = tid & 3;
    const float* gA = A + (size_t)(bm + ra) * K + ca * 4;
    uint32_t dA = ra * 80 + ca * 16;
    const float* gB[4];
    uint32_t dB[4];
    #pragma unroll
    for (int j = 0; j < 4; j++) {
        int rb = (tid + 256 * j) >> 2, cb = (tid + 256 * j) & 3;
        gB[j] = Wt + (size_t)rb * K + cb * 4;
        dB[j] = 5120 + rb * 80 + cb * 16;
    }

    uint32_t a_off = (uint32_t)((lane & 15) * 80 + ((lane & 16) ? 16 : 0));
    uint32_t b_off = (uint32_t)(((lane & 7) + ((lane & 16) ? 8 : 0)) * 80 + ((lane & 8) ? 16 : 0));

    float acc[2][8][4];
    #pragma unroll
    for (int i = 0; i < 2; i++)
        #pragma unroll
        for (int j = 0; j < 8; j++)
            #pragma unroll
            for (int r = 0; r < 4; r++) acc[i][j][r] = 0.0f;

    int NIT = K >> 4;

    #pragma unroll
    for (int s = 0; s < 3; s++) {
        int k0 = s << 4;
        uint32_t sb = smb + s * LSTG_BYTES;
        cpa16(sb + dA, gA + k0);
        #pragma unroll
        for (int j = 0; j < 4; j++) cpa16(sb + dB[j], gB[j] + k0);
        CP_COMMIT();
    }

    for (int it = 0; it < NIT; it++) {
        CP_WAIT2();
        __syncthreads();

        if (it + 3 < NIT) {
            int s = (it + 3) & 3;
            int k0 = (it + 3) << 4;
            uint32_t sb = smb + s * LSTG_BYTES;
            cpa16(sb + dA, gA + k0);
            #pragma unroll
            for (int j = 0; j < 4; j++) cpa16(sb + dB[j], gB[j] + k0);
        }
        CP_COMMIT();

        uint32_t sb = smb + (it & 3) * LSTG_BYTES;
        uint32_t abase = sb + wml * 80 + a_off;
        uint32_t bbase = sb + 5120 + wn * 80 + b_off;

        #pragma unroll
        for (int ksg = 0; ksg < 2; ksg++) {
            uint32_t a[2][4];
            #pragma unroll
            for (int mt = 0; mt < 2; mt++)
                ldsm4(a[mt], abase + mt * 16 * 80 + ksg * 32);
            uint32_t b[8][2];
            #pragma unroll
            for (int ntp = 0; ntp < 4; ntp++) {
                uint32_t r[4];
                ldsm4(r, bbase + ntp * 16 * 80 + ksg * 32);
                b[2 * ntp + 0][0] = r[0]; b[2 * ntp + 0][1] = r[1];
                b[2 * ntp + 1][0] = r[2]; b[2 * ntp + 1][1] = r[3];
            }
            #pragma unroll
            for (int mt = 0; mt < 2; mt++)
                #pragma unroll
                for (int nt = 0; nt < 8; nt++)
                    mma_tf32(acc[mt][nt], a[mt], b[nt]);
        }
    }
    __syncthreads();  // SMEM reuse barrier (stages done) before red[] writes

    // ---- epilogue: v = acc + bias + X; per-row LN over 256 cols ----
    // thread rows: mt*16 + g (r0,r1) and mt*16 + g + 8 (r2,r3), local to warp-m (wml)
    float sum[2][2] = {{0, 0}, {0, 0}};    // [mt][rr]
    float sq [2][2] = {{0, 0}, {0, 0}};
    #pragma unroll
    for (int mt = 0; mt < 2; mt++) {
        #pragma unroll
        for (int nt = 0; nt < 8; nt++) {
            int n = wn + nt * 8 + 2 * tg;
            float b0 = bias[n], b1 = bias[n + 1];
            int mA = bm + wml + mt * 16 + g;
            float2 x0 = *(const float2*)(X + (size_t)mA * 256 + n);
            float2 x1 = *(const float2*)(X + (size_t)(mA + 8) * 256 + n);
            acc[mt][nt][0] += b0 + x0.x;
            acc[mt][nt][1] += b1 + x0.y;
            acc[mt][nt][2] += b0 + x1.x;
            acc[mt][nt][3] += b1 + x1.y;
            sum[mt][0] += acc[mt][nt][0] + acc[mt][nt][1];
            sum[mt][1] += acc[mt][nt][2] + acc[mt][nt][3];
            sq[mt][0]  += acc[mt][nt][0] * acc[mt][nt][0] + acc[mt][nt][1] * acc[mt][nt][1];
            sq[mt][1]  += acc[mt][nt][2] * acc[mt][nt][2] + acc[mt][nt][3] * acc[mt][nt][3];
        }
    }
    // quad reduction over tg (lanes sharing g)
    #pragma unroll
    for (int mt = 0; mt < 2; mt++)
        #pragma unroll
        for (int rr = 0; rr < 2; rr++) {
            #pragma unroll
            for (int o = 1; o < 4; o <<= 1) {
                sum[mt][rr] += __shfl_xor_sync(0xffffffffu, sum[mt][rr], o);
                sq [mt][rr] += __shfl_xor_sync(0xffffffffu, sq [mt][rr], o);
            }
        }
    int nw = wrp & 3;
    if (tg == 0) {
        #pragma unroll
        for (int mt = 0; mt < 2; mt++)
            #pragma unroll
            for (int rr = 0; rr < 2; rr++) {
                int rl = wml + mt * 16 + g + rr * 8;
                red[rl][nw][0] = sum[mt][rr];
                red[rl][nw][1] = sq[mt][rr];
            }
    }
    __syncthreads();

    #pragma unroll
    for (int mt = 0; mt < 2; mt++) {
        #pragma unroll
        for (int rr = 0; rr < 2; rr++) {
            int rl = wml + mt * 16 + g + rr * 8;
            float s  = red[rl][0][0] + red[rl][1][0] + red[rl][2][0] + red[rl][3][0];
            float s2 = red[rl][0][1] + red[rl][1][1] + red[rl][2][1] + red[rl][3][1];
            float mean = s * (1.0f / 256.0f);
            float var  = s2 * (1.0f / 256.0f) - mean * mean;
            float inv  = rsqrtf(var + 1e-5f);
            int m = bm + rl;
            #pragma unroll
            for (int nt = 0; nt < 8; nt++) {
                int n = wn + nt * 8 + 2 * tg;
                float g0 = gma[n], g1 = gma[n + 1];
                float t0 = bta[n], t1 = bta[n + 1];
                float v0 = acc[mt][nt][2 * rr + 0];
                float v1 = acc[mt][nt][2 * rr + 1];
                float o0 = (v0 - mean) * inv * g0 + t0;
                float o1 = (v1 - mean) * inv * g1 + t1;
                float2 ov = {o0, o1};
                *(float2*)(OUT + (size_t)m * 256 + n) = ov;
                if (qpos) {
                    float2 pv = *(const float2*)(pos + (size_t)m * 256 + n);
                    float2 qv = {o0 + pv.x, o1 + pv.y};
                    *(float2*)(qpos + (size_t)m * 256 + n) = qv;
                }
            }
        }
    }
}

// ---------------- deformable attention (one warp per (b,q,h)) ----------------
__global__ void __launch_bounds__(256) deform_kernel(
    const float* __restrict__ voa,
    const float* __restrict__ ref,
    float* __restrict__ out)
{
    const int dims [4] = {64, 32, 16, 8};
    const int bases[4] = {0, 4096, 5120, 5376};

    int bq   = blockIdx.x;
    int h    = threadIdx.x >> 5;
    int lane = threadIdx.x & 31;
    int b = bq / LQ_;
    int q = bq % LQ_;

    const float* lg = voa + (size_t)bq * 640 + 512 + h * 16;
    float xv = (lane < 16) ? lg[lane] : -1e30f;
    float m = xv;
    #pragma unroll
    for (int o = 8; o; o >>= 1) m = fmaxf(m, __shfl_xor_sync(0xffffffffu, m, o));
    float e = (lane < 16) ? __expf(xv - m) : 0.0f;
    float s = e;
    #pragma unroll
    for (int o = 8; o; o >>= 1) s += __shfl_xor_sync(0xffffffffu, s, o);
    float aw = e / s;

    float offv = voa[(size_t)bq * 640 + 256 + h * 32 + lane];
    float refx = ref[q * 2 + 0];
    float refy = ref[q * 2 + 1];

    const float* vb = voa + (size_t)b * LQ_ * 640 + h * HD_ + lane;

    float acc = 0.0f;
    #pragma unroll
    for (int l = 0; l < 4; l++) {
        const int Wl = dims[l];
        const int base = bases[l];
        const float Wf = (float)Wl;
        #pragma unroll
        for (int p = 0; p < 4; p++) {
            int pt = l * 4 + p;
            float ax = __shfl_sync(0xffffffffu, offv, pt * 2 + 0);
            float ay = __shfl_sync(0xffffffffu, offv, pt * 2 + 1);
            float a  = __shfl_sync(0xffffffffu, aw, pt);
            float xf = refx * Wf + ax - 0.5f;
            float yf = refy * Wf + ay - 0.5f;
            float x0f = floorf(xf), y0f = floorf(yf);
            float wx = xf - x0f,   wy = yf - y0f;
            int x0 = (int)x0f, y0 = (int)y0f;
            int x1 = x0 + 1,   y1 = y0 + 1;

            float w00 = (1.f - wy) * (1.f - wx);
            float w01 = (1.f - wy) * wx;
            float w10 = wy * (1.f - wx);
            float w11 = wy * wx;

            if (y0 >= 0 && y0 < Wl) {
                if (x0 >= 0 && x0 < Wl)
                    acc = fmaf(a * w00, vb[(size_t)(base + y0 * Wl + x0) * 640], acc);
                if (x1 >= 0 && x1 < Wl)
                    acc = fmaf(a * w01, vb[(size_t)(base + y0 * Wl + x1) * 640], acc);
            }
            if (y1 >= 0 && y1 < Wl) {
                if (x0 >= 0 && x0 < Wl)
                    acc = fmaf(a * w10, vb[(size_t)(base + y1 * Wl + x0) * 640], acc);
                if (x1 >= 0 && x1 < Wl)
                    acc = fmaf(a * w11, vb[(size_t)(base + y1 * Wl + x1) * 640], acc);
            }
        }
    }
    out[(size_t)bq * 256 + h * HD_ + lane] = acc;
}

// ---------------- host orchestration ----------------
static float* sym_ptr(const void* sym)
{
    void* p = nullptr;
    cudaGetSymbolAddress(&p, sym);
    return (float*)p;
}

extern "C" void kernel_launch(void* const* d_in, const int* in_sizes, int n_in,
                              void* d_out, int out_size)
{
    bool interleaved = (in_sizes[1] == in_sizes[0]);
    const float* srcs[4];
    const float* poss[4];
    for (int l = 0; l < 4; l++) {
        srcs[l] = (const float*)d_in[interleaved ? 2 * l     : l];
        poss[l] = (const float*)d_in[interleaved ? 2 * l + 1 : 4 + l];
    }
    const float* level_embed = (const float*)d_in[8];
    const float* W_off  = (const float*)d_in[9];
    const float* b_off  = (const float*)d_in[10];
    const float* W_attn = (const float*)d_in[11];
    const float* b_attn = (const float*)d_in[12];
    const float* W_v    = (const float*)d_in[13];
    const float* b_v    = (const float*)d_in[14];
    const float* W_o    = (const float*)d_in[15];
    const float* b_o    = (const float*)d_in[16];
    const float* ln1_g  = (const float*)d_in[17];
    const float* ln1_b  = (const float*)d_in[18];
    const float* W_fc1  = (const float*)d_in[19];
    const float* b_fc1  = (const float*)d_in[20];
    const float* W_fc2  = (const float*)d_in[21];
    const float* b_fc2  = (const float*)d_in[22];
    const float* ln2_g  = (const float*)d_in[23];
    const float* ln2_b  = (const float*)d_in[24];

    float* pos  = sym_ptr(g_pos);
    float* out  = sym_ptr(g_out);
    float* qpos = sym_ptr(g_qpos);
    float* voa  = sym_ptr(g_voa);
    float* defo = sym_ptr(g_def);
    float* ffn  = sym_ptr(g_ffn);
    float* ref  = sym_ptr(g_ref);
    float* wvoa = sym_ptr(g_wt_voa);
    float* wo   = sym_ptr(g_wt_o);
    float* wf1  = sym_ptr(g_wt_f1);
    float* wf2  = sym_ptr(g_wt_f2);
    float* bc   = sym_ptr(g_bc);

    cudaFuncSetAttribute(tgemm_kernel<0>, cudaFuncAttributeMaxDynamicSharedMemorySize, GEMM_SMEM);
    cudaFuncSetAttribute(tgemm_kernel<1>, cudaFuncAttributeMaxDynamicSharedMemorySize, GEMM_SMEM);
    cudaFuncSetAttribute(tgemm_ln_kernel, cudaFuncAttributeMaxDynamicSharedMemorySize, LGEMM_SMEM);

    dim3 tb(32, 8);
    flatten_all_kernel<<<dim3(170, D_ / 32, B_), tb>>>(
        srcs[0], srcs[1], srcs[2], srcs[3],
        poss[0], poss[1], poss[2], poss[3],
        level_embed, out, pos, qpos);
    ref_kernel<<<(LQ_ + 255) / 256, 256>>>(ref);

    wtrans_kernel<<<dim3(8,  8,  NL_), tb>>>(W_v,    wvoa,             256, 256,  65536,  640*256);
    wtrans_kernel<<<dim3(8,  8,  NL_), tb>>>(W_off,  wvoa + 256*256,   256, 256,  65536,  640*256);
    wtrans_kernel<<<dim3(4,  8,  NL_), tb>>>(W_attn, wvoa + 512*256,   256, 128,  32768,  640*256);
    wtrans_kernel<<<dim3(8,  8,  NL_), tb>>>(W_o,    wo,               256, 256,  65536,  256*256);
    wtrans_kernel<<<dim3(32, 8,  NL_), tb>>>(W_fc1,  wf1,              256, 1024, 262144, 1024*256);
    wtrans_kernel<<<dim3(8,  32, NL_), tb>>>(W_fc2,  wf2,              1024,256,  262144, 256*1024);
    bcomb_kernel<<<(NL_ * 640 + 255) / 256, 256>>>(b_v, b_off, b_attn, bc);

    const int MB = MROWS / 128; // 170
    const int LB = MROWS / 64;  // 340
    for (int i = 0; i < NL_; i++) {
        const float* Wvoa = wvoa  + (size_t)i * 640 * 256;
        const float* Bc   = bc    + (size_t)i * 640;
        const float* Wo   = wo    + (size_t)i * 256 * 256;
        const float* bo   = b_o   + (size_t)i * D_;
        const float* Wf1  = wf1   + (size_t)i * 1024 * 256;
        const float* bf1  = b_fc1 + (size_t)i * FF_;
        const float* Wf2  = wf2   + (size_t)i * 256 * 1024;
        const float* bf2  = b_fc2 + (size_t)i * D_;

        tgemm_kernel<0><<<dim3(5, MB), 256, GEMM_SMEM>>>(out, qpos, Wvoa, Bc, voa, 640, 256, 2);

        deform_kernel<<<MROWS, 256>>>(voa, ref, defo);

        // O-proj + LN1 fused
        tgemm_ln_kernel<<<LB, 256, LGEMM_SMEM>>>(defo, Wo, bo, out,
            ln1_g + i * D_, ln1_b + i * D_, out, nullptr, nullptr, 256);

        tgemm_kernel<1><<<dim3(8, MB), 256, GEMM_SMEM>>>(out, out, Wf1, bf1, ffn, 1024, 256, 0);

        // FC2 + LN2 fused (+ qpos for next layer)
        if (i == NL_ - 1) {
            tgemm_ln_kernel<<<LB, 256, LGEMM_SMEM>>>(ffn, Wf2, bf2, out,
                ln2_g + i * D_, ln2_b + i * D_, (float*)d_out, nullptr, nullptr, 1024);
        } else {
            tgemm_ln_kernel<<<LB, 256, LGEMM_SMEM>>>(ffn, Wf2, bf2, out,
                ln2_g + i * D_, ln2_b + i * D_, out, pos, qpos, 1024);
        }
    }
}